// round 3
// baseline (speedup 1.0000x reference)
#include <cuda_runtime.h>

#define BB 2
#define SS 2048
#define DD 1024
#define HH 16
#define HD 64
#define MROWS (BB*SS)   // 4096
#define N_QKV (3*DD)    // 3072

// Scratch (device globals — no allocation allowed)
__device__ float g_q[BB*HH*SS*HD];   // [B,H,S,HD]
__device__ float g_k[BB*HH*SS*HD];
__device__ float g_v[BB*HH*SS*HD];
__device__ float g_y[BB*SS*DD];      // [B,S,D]

// ---------------------------------------------------------------------------
// 128x128x8 SGEMM core. 256 threads, 8x8 per-thread tile (2x2 groups of 4x4).
// ---------------------------------------------------------------------------

// QKV GEMM: C = x @ w_attn + b_attn, scattered to g_q/g_k/g_v in [B,H,S,HD]
__global__ __launch_bounds__(256) void qkv_gemm(const float* __restrict__ A,
                                                const float* __restrict__ Bm,
                                                const float* __restrict__ bias) {
    const int K = DD, N = N_QKV;
    __shared__ float As[8][128];
    __shared__ float Bs[8][128];

    int t  = threadIdx.x;
    int tx = t & 15, ty = t >> 4;
    int m0 = blockIdx.y * 128;
    int n0 = blockIdx.x * 128;

    float acc[8][8];
#pragma unroll
    for (int i = 0; i < 8; i++)
#pragma unroll
        for (int j = 0; j < 8; j++) acc[i][j] = 0.f;

    int a_row = t >> 1;         // 0..127
    int a_k4  = (t & 1) * 4;    // 0 or 4
    int b_k   = t >> 5;         // 0..7
    int b_n4  = (t & 31) * 4;   // 0..124

    const float* Aptr = A  + (m0 + a_row) * K + a_k4;
    const float* Bptr = Bm + b_k * N + n0 + b_n4;

    float4 av = *(const float4*)(Aptr);
    float4 bv = *(const float4*)(Bptr);

    for (int kb = 0; kb < K; kb += 8) {
        __syncthreads();
        As[a_k4 + 0][a_row] = av.x;
        As[a_k4 + 1][a_row] = av.y;
        As[a_k4 + 2][a_row] = av.z;
        As[a_k4 + 3][a_row] = av.w;
        *(float4*)&Bs[b_k][b_n4] = bv;
        __syncthreads();

        if (kb + 8 < K) {  // prefetch next tile (overlaps with compute)
            av = *(const float4*)(Aptr + kb + 8);
            bv = *(const float4*)(Bptr + (kb + 8) * N);
        }

#pragma unroll
        for (int k = 0; k < 8; k++) {
            float4 a0 = *(float4*)&As[k][ty * 4];
            float4 a1 = *(float4*)&As[k][64 + ty * 4];
            float4 b0 = *(float4*)&Bs[k][tx * 4];
            float4 b1 = *(float4*)&Bs[k][64 + tx * 4];
            float ar[8] = {a0.x, a0.y, a0.z, a0.w, a1.x, a1.y, a1.z, a1.w};
            float br[8] = {b0.x, b0.y, b0.z, b0.w, b1.x, b1.y, b1.z, b1.w};
#pragma unroll
            for (int i = 0; i < 8; i++)
#pragma unroll
                for (int j = 0; j < 8; j++)
                    acc[i][j] = fmaf(ar[i], br[j], acc[i][j]);
        }
    }

    // Epilogue: add bias, scatter into per-head layout.
#pragma unroll
    for (int ii = 0; ii < 8; ii++) {
        int mi = m0 + ((ii < 4) ? (ty * 4 + ii) : (64 + ty * 4 + ii - 4));
        int b    = mi >> 11;        // / 2048
        int sidx = mi & 2047;
#pragma unroll
        for (int jj = 0; jj < 8; jj++) {
            int nj = n0 + ((jj < 4) ? (tx * 4 + jj) : (64 + tx * 4 + jj - 4));
            float val = acc[ii][jj] + bias[nj];
            int which = nj >> 10;       // 0:q 1:k 2:v
            int rem   = nj & 1023;
            int h     = rem >> 6;
            int d     = rem & 63;
            float* dst = (which == 0) ? g_q : (which == 1) ? g_k : g_v;
            dst[(((b * HH + h) << 11) + sidx) * HD + d] = val;
        }
    }
}

// Output projection: d_out = g_y @ w_proj + b_proj
__global__ __launch_bounds__(256) void proj_gemm(const float* __restrict__ Bm,
                                                 const float* __restrict__ bias,
                                                 float* __restrict__ Cout) {
    const int K = DD, N = DD;
    __shared__ float As[8][128];
    __shared__ float Bs[8][128];

    int t  = threadIdx.x;
    int tx = t & 15, ty = t >> 4;
    int m0 = blockIdx.y * 128;
    int n0 = blockIdx.x * 128;

    float acc[8][8];
#pragma unroll
    for (int i = 0; i < 8; i++)
#pragma unroll
        for (int j = 0; j < 8; j++) acc[i][j] = 0.f;

    int a_row = t >> 1;
    int a_k4  = (t & 1) * 4;
    int b_k   = t >> 5;
    int b_n4  = (t & 31) * 4;

    const float* Aptr = g_y + (m0 + a_row) * K + a_k4;
    const float* Bptr = Bm + b_k * N + n0 + b_n4;

    float4 av = *(const float4*)(Aptr);
    float4 bv = *(const float4*)(Bptr);

    for (int kb = 0; kb < K; kb += 8) {
        __syncthreads();
        As[a_k4 + 0][a_row] = av.x;
        As[a_k4 + 1][a_row] = av.y;
        As[a_k4 + 2][a_row] = av.z;
        As[a_k4 + 3][a_row] = av.w;
        *(float4*)&Bs[b_k][b_n4] = bv;
        __syncthreads();

        if (kb + 8 < K) {
            av = *(const float4*)(Aptr + kb + 8);
            bv = *(const float4*)(Bptr + (kb + 8) * N);
        }

#pragma unroll
        for (int k = 0; k < 8; k++) {
            float4 a0 = *(float4*)&As[k][ty * 4];
            float4 a1 = *(float4*)&As[k][64 + ty * 4];
            float4 b0 = *(float4*)&Bs[k][tx * 4];
            float4 b1 = *(float4*)&Bs[k][64 + tx * 4];
            float ar[8] = {a0.x, a0.y, a0.z, a0.w, a1.x, a1.y, a1.z, a1.w};
            float br[8] = {b0.x, b0.y, b0.z, b0.w, b1.x, b1.y, b1.z, b1.w};
#pragma unroll
            for (int i = 0; i < 8; i++)
#pragma unroll
                for (int j = 0; j < 8; j++)
                    acc[i][j] = fmaf(ar[i], br[j], acc[i][j]);
        }
    }

#pragma unroll
    for (int ii = 0; ii < 8; ii++) {
        int mi = m0 + ((ii < 4) ? (ty * 4 + ii) : (64 + ty * 4 + ii - 4));
#pragma unroll
        for (int jj = 0; jj < 8; jj++) {
            int nj = n0 + ((jj < 4) ? (tx * 4 + jj) : (64 + tx * 4 + jj - 4));
            Cout[mi * N + nj] = acc[ii][jj] + bias[nj];
        }
    }
}

// ---------------------------------------------------------------------------
// Flash attention: per (b,h, 64-row q tile). Causal, online softmax, fp32.
// smem: Q,K,V,P tiles each 64 x 65 floats (pad kills bank conflicts).
// ---------------------------------------------------------------------------
#define ATT_STRIDE 65
#define ATT_SMEM (4 * 64 * ATT_STRIDE * sizeof(float))

__global__ __launch_bounds__(256) void attn_kernel() {
    extern __shared__ float sm[];
    float* Qs = sm;
    float* Ks = sm + 64 * ATT_STRIDE;
    float* Vs = sm + 2 * 64 * ATT_STRIDE;
    float* Ps = sm + 3 * 64 * ATT_STRIDE;

    int t  = threadIdx.x;
    int tx = t & 15, ty = t >> 4;
    int qt = blockIdx.x;   // 0..31 q tile
    int bh = blockIdx.y;   // 0..31 = b*H + h

    const float* qb  = g_q + (size_t)bh * (SS * HD) + (size_t)qt * 64 * HD;
    const float* kb0 = g_k + (size_t)bh * (SS * HD);
    const float* vb0 = g_v + (size_t)bh * (SS * HD);

    // Load Q tile (coalesced: each thread 16 contiguous floats)
    {
        int r  = t >> 2;
        int c0 = (t & 3) * 16;
#pragma unroll
        for (int q = 0; q < 4; q++) {
            float4 v = *(const float4*)(qb + r * HD + c0 + q * 4);
            Qs[r * ATT_STRIDE + c0 + q * 4 + 0] = v.x;
            Qs[r * ATT_STRIDE + c0 + q * 4 + 1] = v.y;
            Qs[r * ATT_STRIDE + c0 + q * 4 + 2] = v.z;
            Qs[r * ATT_STRIDE + c0 + q * 4 + 3] = v.w;
        }
    }

    float m_i[4], l_i[4], o[4][4];
#pragma unroll
    for (int i = 0; i < 4; i++) {
        m_i[i] = -1e30f; l_i[i] = 0.f;
#pragma unroll
        for (int j = 0; j < 4; j++) o[i][j] = 0.f;
    }

    for (int kt = 0; kt <= qt; kt++) {
        __syncthreads();   // prev PV done before K/V/P reuse
        {
            int r  = t >> 2;
            int c0 = (t & 3) * 16;
            const float* kp = kb0 + (size_t)kt * 64 * HD;
            const float* vp = vb0 + (size_t)kt * 64 * HD;
#pragma unroll
            for (int q = 0; q < 4; q++) {
                float4 kv = *(const float4*)(kp + r * HD + c0 + q * 4);
                Ks[r * ATT_STRIDE + c0 + q * 4 + 0] = kv.x;
                Ks[r * ATT_STRIDE + c0 + q * 4 + 1] = kv.y;
                Ks[r * ATT_STRIDE + c0 + q * 4 + 2] = kv.z;
                Ks[r * ATT_STRIDE + c0 + q * 4 + 3] = kv.w;
                float4 vv = *(const float4*)(vp + r * HD + c0 + q * 4);
                Vs[r * ATT_STRIDE + c0 + q * 4 + 0] = vv.x;
                Vs[r * ATT_STRIDE + c0 + q * 4 + 1] = vv.y;
                Vs[r * ATT_STRIDE + c0 + q * 4 + 2] = vv.z;
                Vs[r * ATT_STRIDE + c0 + q * 4 + 3] = vv.w;
            }
        }
        __syncthreads();

        // S = Q @ K^T (4x4 per thread)
        float sreg[4][4];
#pragma unroll
        for (int i = 0; i < 4; i++)
#pragma unroll
            for (int j = 0; j < 4; j++) sreg[i][j] = 0.f;

        for (int d = 0; d < 64; d++) {
            float qa[4], ka[4];
#pragma unroll
            for (int i = 0; i < 4; i++) qa[i] = Qs[(ty * 4 + i) * ATT_STRIDE + d];
#pragma unroll
            for (int j = 0; j < 4; j++) ka[j] = Ks[(tx * 4 + j) * ATT_STRIDE + d];
#pragma unroll
            for (int i = 0; i < 4; i++)
#pragma unroll
                for (int j = 0; j < 4; j++)
                    sreg[i][j] = fmaf(qa[i], ka[j], sreg[i][j]);
        }

        const float scale = 0.125f;  // 1/sqrt(64)
        if (kt == qt) {
#pragma unroll
            for (int i = 0; i < 4; i++)
#pragma unroll
                for (int j = 0; j < 4; j++)
                    sreg[i][j] = (tx * 4 + j <= ty * 4 + i) ? sreg[i][j] * scale : -1e30f;
        } else {
#pragma unroll
            for (int i = 0; i < 4; i++)
#pragma unroll
                for (int j = 0; j < 4; j++) sreg[i][j] *= scale;
        }

        // Online softmax per row (reduce across the 16-lane tx group)
#pragma unroll
        for (int i = 0; i < 4; i++) {
            float rm = fmaxf(fmaxf(sreg[i][0], sreg[i][1]), fmaxf(sreg[i][2], sreg[i][3]));
#pragma unroll
            for (int off = 8; off; off >>= 1)
                rm = fmaxf(rm, __shfl_xor_sync(0xffffffffu, rm, off));
            float mn = fmaxf(m_i[i], rm);
            float fi = __expf(m_i[i] - mn);
            float rs = 0.f;
#pragma unroll
            for (int j = 0; j < 4; j++) {
                float p = __expf(sreg[i][j] - mn);
                sreg[i][j] = p;
                rs += p;
            }
#pragma unroll
            for (int off = 8; off; off >>= 1)
                rs += __shfl_xor_sync(0xffffffffu, rs, off);
            l_i[i] = l_i[i] * fi + rs;
            m_i[i] = mn;
#pragma unroll
            for (int j = 0; j < 4; j++) {
                o[i][j] *= fi;
                Ps[(ty * 4 + i) * ATT_STRIDE + tx * 4 + j] = sreg[i][j];
            }
        }
        __syncthreads();

        // O += P @ V
        for (int k = 0; k < 64; k++) {
            float pa[4], va[4];
#pragma unroll
            for (int i = 0; i < 4; i++) pa[i] = Ps[(ty * 4 + i) * ATT_STRIDE + k];
#pragma unroll
            for (int j = 0; j < 4; j++) va[j] = Vs[k * ATT_STRIDE + tx * 4 + j];
#pragma unroll
            for (int i = 0; i < 4; i++)
#pragma unroll
                for (int j = 0; j < 4; j++)
                    o[i][j] = fmaf(pa[i], va[j], o[i][j]);
        }
    }

    // Write back to [B,S,D] layout for the projection GEMM
    int b = bh >> 4, h = bh & 15;
#pragma unroll
    for (int i = 0; i < 4; i++) {
        float inv = 1.f / l_i[i];
        int srow = qt * 64 + ty * 4 + i;
        float* yp = g_y + ((size_t)(b * SS + srow)) * DD + h * HD + tx * 4;
#pragma unroll
        for (int j = 0; j < 4; j++) yp[j] = o[i][j] * inv;
    }
}

// ---------------------------------------------------------------------------

extern "C" void kernel_launch(void* const* d_in, const int* in_sizes, int n_in,
                              void* d_out, int out_size) {
    const float* x      = (const float*)d_in[0];  // [2,2048,1024]
    const float* w_attn = (const float*)d_in[1];  // [1024,3072]
    const float* b_attn = (const float*)d_in[2];  // [3072]
    const float* w_proj = (const float*)d_in[3];  // [1024,1024]
    const float* b_proj = (const float*)d_in[4];  // [1024]
    float* out = (float*)d_out;

    cudaFuncSetAttribute(attn_kernel, cudaFuncAttributeMaxDynamicSharedMemorySize,
                         (int)ATT_SMEM);

    // 1) QKV projection + head-layout scatter
    qkv_gemm<<<dim3(N_QKV / 128, MROWS / 128), 256>>>(x, w_attn, b_attn);

    // 2) Causal flash attention
    attn_kernel<<<dim3(SS / 64, BB * HH), 256, ATT_SMEM>>>();

    // 3) Output projection
    proj_gemm<<<dim3(DD / 128, MROWS / 128), 256>>>(w_proj, b_proj, out);
}

// round 5
// speedup vs baseline: 1.1495x; 1.1495x over previous
#include <cuda_runtime.h>
#include <cstdint>

#define BB 2
#define SS 2048
#define DD 1024
#define HH 16
#define HD 64
#define MROWS (BB*SS)   // 4096
#define N_QKV (3*DD)    // 3072
#define KDIM 1024

// Scratch (device globals — no allocation allowed)
__device__ float g_q[BB*HH*SS*HD];   // [B,H,S,HD]
__device__ float g_k[BB*HH*SS*HD];
__device__ float g_v[BB*HH*SS*HD];
__device__ float g_y[BB*SS*DD];      // [B,S,D]

__device__ __forceinline__ uint32_t f2tf(float x) {  // round-to-nearest tf32
    uint32_t r;
    asm("cvt.rna.tf32.f32 %0, %1;" : "=r"(r) : "f"(x));
    return r;
}

#define MMA_TF32(d, a, b) \
    asm volatile("mma.sync.aligned.m16n8k8.row.col.f32.tf32.tf32.f32 " \
        "{%0,%1,%2,%3}, {%4,%5,%6,%7}, {%8,%9}, {%0,%1,%2,%3};" \
        : "+f"((d)[0]), "+f"((d)[1]), "+f"((d)[2]), "+f"((d)[3]) \
        : "r"((a)[0]), "r"((a)[1]), "r"((a)[2]), "r"((a)[3]), \
          "r"((b)[0]), "r"((b)[1]))

// ---------------------------------------------------------------------------
// tf32 mma.sync GEMM: C[128x128 tile] = A[M,1024] @ w[1024,N] + bias
// SMEM tiles stored fragment-major:
//   A chunk: 8 m-blocks(16) x 4 k-blocks(8); block = 32 lanes x 4 regs (LDS.128)
//   B chunk: 16 n-blocks(8) x 4 k-blocks(8); block = 32 lanes x 2 regs (LDS.64)
// Fragment maps (PTX m16n8k8 tf32):
//   A (r,c): lane=(r&7)*4+(c&3), reg=(r>=8)+2*(c>=4)
//   B (k,n): lane=n*4+(k&3),     reg=k>>2
//   C (r,c): lane=(r&7)*4+(c>>1), reg=(c&1)+2*(r>=8)
// ---------------------------------------------------------------------------
#define GEMM_SMEM (65536)
#define NCHUNK (KDIM/32)

template<int N, bool QKV>
__global__ __launch_bounds__(256) void gemm_mma(const float* __restrict__ A,
                                                const float* __restrict__ Bw,
                                                const float* __restrict__ bias,
                                                float* __restrict__ Cout) {
    extern __shared__ float sm[];
    // layout: As[2][4096], Bs[2][4096]
    float* Asm = sm;          // 2 x 4096
    float* Bsm = sm + 8192;   // 2 x 4096

    const int t = threadIdx.x;
    const int wid = t >> 5, lane = t & 31;
    const int warp_m = wid & 3;     // 4 warps along M
    const int warp_n = wid >> 2;    // 2 warps along N
    const int m0 = blockIdx.y * 128;
    const int n0 = blockIdx.x * 128;

    const float* Ap = QKV ? A : (const float*)g_y;

    // staging thread mapping
    const int a_m  = t >> 1;              // 0..127
    const int a_kb = (t & 1) * 16;        // 0 or 16 (k base within chunk)
    const int b_k  = t >> 3;              // 0..31
    const int b_n0 = (t & 7) * 16;        // 0..120

    // precomputed A store slots for its 4 float4s (reg + lane-base const per q)
    const int a_r = a_m & 15;
    const int a_mb = a_m >> 4;
    const int a_lanebase = (a_m & 7) * 4;

    const int b_kb = b_k >> 3;
    const int b_kc = b_k & 7;
    const int b_reg = b_kc >> 2;
    const int b_lo = b_kc & 3;

    float4 avr[2], bvr[4];

    // ---- ldg(chunk) ----
#define LDG_CHUNK(c) do { \
        const float* Arow = Ap + (size_t)(m0 + a_m) * KDIM + (c) * 32 + a_kb; \
        avr[0] = *(const float4*)(Arow); \
        avr[1] = *(const float4*)(Arow + 4); \
        /* second half of this thread's 16 k: */ \
        avr[0].x = avr[0].x; /* keep */ \
        bvr[0] = *(const float4*)(Bw + (size_t)((c) * 32 + b_k) * N + n0 + b_n0); \
        bvr[1] = *(const float4*)(Bw + (size_t)((c) * 32 + b_k) * N + n0 + b_n0 + 4); \
        bvr[2] = *(const float4*)(Bw + (size_t)((c) * 32 + b_k) * N + n0 + b_n0 + 8); \
        bvr[3] = *(const float4*)(Bw + (size_t)((c) * 32 + b_k) * N + n0 + b_n0 + 12); \
        avr2[0] = *(const float4*)(Arow + 8); \
        avr2[1] = *(const float4*)(Arow + 12); \
    } while (0)

    float4 avr2[2];

    // ---- sts(buf) ----
#define STS_CHUNK(buf) do { \
        float* Ad = Asm + (buf) * 4096; \
        float* Bd = Bsm + (buf) * 4096; \
        _Pragma("unroll") \
        for (int q = 0; q < 4; q++) { \
            float4 v = (q < 2) ? avr[q] : avr2[q - 2]; \
            int k0 = a_kb + q * 4; \
            int kb = k0 >> 3; \
            int reg = ((a_r >= 8) ? 1 : 0) + (((k0 & 7) >= 4) ? 2 : 0); \
            float* blk = Ad + (a_mb * 4 + kb) * 128; \
            blk[(a_lanebase + 0) * 4 + reg] = __uint_as_float(f2tf(v.x)); \
            blk[(a_lanebase + 1) * 4 + reg] = __uint_as_float(f2tf(v.y)); \
            blk[(a_lanebase + 2) * 4 + reg] = __uint_as_float(f2tf(v.z)); \
            blk[(a_lanebase + 3) * 4 + reg] = __uint_as_float(f2tf(v.w)); \
        } \
        _Pragma("unroll") \
        for (int q = 0; q < 4; q++) { \
            float4 v = bvr[q]; \
            int nb = (b_n0 + q * 4) >> 3; \
            int nr = (b_n0 + q * 4) & 7;  /* 0 or 4 */ \
            float* blk = Bd + (nb * 4 + b_kb) * 64; \
            blk[((nr + 0) * 4 + b_lo) * 2 + b_reg] = __uint_as_float(f2tf(v.x)); \
            blk[((nr + 1) * 4 + b_lo) * 2 + b_reg] = __uint_as_float(f2tf(v.y)); \
            blk[((nr + 2) * 4 + b_lo) * 2 + b_reg] = __uint_as_float(f2tf(v.z)); \
            blk[((nr + 3) * 4 + b_lo) * 2 + b_reg] = __uint_as_float(f2tf(v.w)); \
        } \
    } while (0)

    float acc[2][8][4];
#pragma unroll
    for (int i = 0; i < 2; i++)
#pragma unroll
        for (int j = 0; j < 8; j++)
#pragma unroll
            for (int r = 0; r < 4; r++) acc[i][j][r] = 0.f;

    LDG_CHUNK(0);
    STS_CHUNK(0);
    __syncthreads();

#pragma unroll 1
    for (int c = 0; c < NCHUNK; c++) {
        const int buf = c & 1;
        if (c + 1 < NCHUNK) LDG_CHUNK(c + 1);

        const float* Ab = Asm + buf * 4096;
        const float* Bb = Bsm + buf * 4096;
#pragma unroll
        for (int kb = 0; kb < 4; kb++) {
            uint32_t af[2][4];
            uint32_t bf[8][2];
#pragma unroll
            for (int i = 0; i < 2; i++) {
                float4 v = *(const float4*)(Ab + ((warp_m * 2 + i) * 4 + kb) * 128 + lane * 4);
                af[i][0] = __float_as_uint(v.x);
                af[i][1] = __float_as_uint(v.y);
                af[i][2] = __float_as_uint(v.z);
                af[i][3] = __float_as_uint(v.w);
            }
#pragma unroll
            for (int j = 0; j < 8; j++) {
                float2 v = *(const float2*)(Bb + ((warp_n * 8 + j) * 4 + kb) * 64 + lane * 2);
                bf[j][0] = __float_as_uint(v.x);
                bf[j][1] = __float_as_uint(v.y);
            }
#pragma unroll
            for (int i = 0; i < 2; i++)
#pragma unroll
                for (int j = 0; j < 8; j++)
                    MMA_TF32(acc[i][j], af[i], bf[j]);
        }

        if (c + 1 < NCHUNK) STS_CHUNK((c + 1) & 1);
        __syncthreads();
    }

    // Epilogue
    const int r0 = lane >> 2;
    const int cp = (lane & 3) * 2;
#pragma unroll
    for (int i = 0; i < 2; i++) {
        const int mbase = m0 + warp_m * 32 + i * 16;
#pragma unroll
        for (int j = 0; j < 8; j++) {
            const int n = n0 + warp_n * 64 + j * 8 + cp;
            const float bx = bias[n], by = bias[n + 1];
            float2 v01 = make_float2(acc[i][j][0] + bx, acc[i][j][1] + by);
            float2 v23 = make_float2(acc[i][j][2] + bx, acc[i][j][3] + by);
            if (QKV) {
                const int which = n >> 10;
                const int h = (n >> 6) & 15;
                const int d = n & 63;
                float* dst = (which == 0) ? g_q : (which == 1) ? g_k : g_v;
                int m1 = mbase + r0;
                int m2 = m1 + 8;
                *(float2*)(dst + ((((size_t)(m1 >> 11) * HH + h) * SS + (m1 & 2047)) * HD + d)) = v01;
                *(float2*)(dst + ((((size_t)(m2 >> 11) * HH + h) * SS + (m2 & 2047)) * HD + d)) = v23;
            } else {
                *(float2*)(Cout + (size_t)(mbase + r0) * DD + n) = v01;
                *(float2*)(Cout + (size_t)(mbase + r0 + 8) * DD + n) = v23;
            }
        }
    }
#undef LDG_CHUNK
#undef STS_CHUNK
}

// ---------------------------------------------------------------------------
// Flash attention (fp32, unchanged — next round's target)
// ---------------------------------------------------------------------------
#define ATT_STRIDE 65
#define ATT_SMEM (4 * 64 * ATT_STRIDE * sizeof(float))

__global__ __launch_bounds__(256) void attn_kernel() {
    extern __shared__ float smf[];
    float* Qs = smf;
    float* Ks = smf + 64 * ATT_STRIDE;
    float* Vs = smf + 2 * 64 * ATT_STRIDE;
    float* Ps = smf + 3 * 64 * ATT_STRIDE;

    int t = threadIdx.x;
    int tx = t & 15, ty = t >> 4;
    int qt = blockIdx.x;
    int bh = blockIdx.y;

    const float* qb  = g_q + (size_t)bh * (SS * HD) + (size_t)qt * 64 * HD;
    const float* kb0 = g_k + (size_t)bh * (SS * HD);
    const float* vb0 = g_v + (size_t)bh * (SS * HD);

    {
        int r = t >> 2, c0 = (t & 3) * 16;
#pragma unroll
        for (int q = 0; q < 4; q++) {
            float4 v = *(const float4*)(qb + r * HD + c0 + q * 4);
            Qs[r * ATT_STRIDE + c0 + q * 4 + 0] = v.x;
            Qs[r * ATT_STRIDE + c0 + q * 4 + 1] = v.y;
            Qs[r * ATT_STRIDE + c0 + q * 4 + 2] = v.z;
            Qs[r * ATT_STRIDE + c0 + q * 4 + 3] = v.w;
        }
    }

    float m_i[4], l_i[4], o[4][4];
#pragma unroll
    for (int i = 0; i < 4; i++) {
        m_i[i] = -1e30f; l_i[i] = 0.f;
#pragma unroll
        for (int j = 0; j < 4; j++) o[i][j] = 0.f;
    }

    for (int kt = 0; kt <= qt; kt++) {
        __syncthreads();
        {
            int r = t >> 2, c0 = (t & 3) * 16;
            const float* kp = kb0 + (size_t)kt * 64 * HD;
            const float* vp = vb0 + (size_t)kt * 64 * HD;
#pragma unroll
            for (int q = 0; q < 4; q++) {
                float4 kv = *(const float4*)(kp + r * HD + c0 + q * 4);
                Ks[r * ATT_STRIDE + c0 + q * 4 + 0] = kv.x;
                Ks[r * ATT_STRIDE + c0 + q * 4 + 1] = kv.y;
                Ks[r * ATT_STRIDE + c0 + q * 4 + 2] = kv.z;
                Ks[r * ATT_STRIDE + c0 + q * 4 + 3] = kv.w;
                float4 vv = *(const float4*)(vp + r * HD + c0 + q * 4);
                Vs[r * ATT_STRIDE + c0 + q * 4 + 0] = vv.x;
                Vs[r * ATT_STRIDE + c0 + q * 4 + 1] = vv.y;
                Vs[r * ATT_STRIDE + c0 + q * 4 + 2] = vv.z;
                Vs[r * ATT_STRIDE + c0 + q * 4 + 3] = vv.w;
            }
        }
        __syncthreads();

        float sreg[4][4];
#pragma unroll
        for (int i = 0; i < 4; i++)
#pragma unroll
            for (int j = 0; j < 4; j++) sreg[i][j] = 0.f;

        for (int d = 0; d < 64; d++) {
            float qa[4], ka[4];
#pragma unroll
            for (int i = 0; i < 4; i++) qa[i] = Qs[(ty * 4 + i) * ATT_STRIDE + d];
#pragma unroll
            for (int j = 0; j < 4; j++) ka[j] = Ks[(tx * 4 + j) * ATT_STRIDE + d];
#pragma unroll
            for (int i = 0; i < 4; i++)
#pragma unroll
                for (int j = 0; j < 4; j++)
                    sreg[i][j] = fmaf(qa[i], ka[j], sreg[i][j]);
        }

        const float scale = 0.125f;
        if (kt == qt) {
#pragma unroll
            for (int i = 0; i < 4; i++)
#pragma unroll
                for (int j = 0; j < 4; j++)
                    sreg[i][j] = (tx * 4 + j <= ty * 4 + i) ? sreg[i][j] * scale : -1e30f;
        } else {
#pragma unroll
            for (int i = 0; i < 4; i++)
#pragma unroll
                for (int j = 0; j < 4; j++) sreg[i][j] *= scale;
        }

#pragma unroll
        for (int i = 0; i < 4; i++) {
            float rm = fmaxf(fmaxf(sreg[i][0], sreg[i][1]), fmaxf(sreg[i][2], sreg[i][3]));
#pragma unroll
            for (int off = 8; off; off >>= 1)
                rm = fmaxf(rm, __shfl_xor_sync(0xffffffffu, rm, off));
            float mn = fmaxf(m_i[i], rm);
            float fi = __expf(m_i[i] - mn);
            float rs = 0.f;
#pragma unroll
            for (int j = 0; j < 4; j++) {
                float p = __expf(sreg[i][j] - mn);
                sreg[i][j] = p;
                rs += p;
            }
#pragma unroll
            for (int off = 8; off; off >>= 1)
                rs += __shfl_xor_sync(0xffffffffu, rs, off);
            l_i[i] = l_i[i] * fi + rs;
            m_i[i] = mn;
#pragma unroll
            for (int j = 0; j < 4; j++) {
                o[i][j] *= fi;
                Ps[(ty * 4 + i) * ATT_STRIDE + tx * 4 + j] = sreg[i][j];
            }
        }
        __syncthreads();

        for (int k = 0; k < 64; k++) {
            float pa[4], va[4];
#pragma unroll
            for (int i = 0; i < 4; i++) pa[i] = Ps[(ty * 4 + i) * ATT_STRIDE + k];
#pragma unroll
            for (int j = 0; j < 4; j++) va[j] = Vs[k * ATT_STRIDE + tx * 4 + j];
#pragma unroll
            for (int i = 0; i < 4; i++)
#pragma unroll
                for (int j = 0; j < 4; j++)
                    o[i][j] = fmaf(pa[i], va[j], o[i][j]);
        }
    }

    int b = bh >> 4, h = bh & 15;
#pragma unroll
    for (int i = 0; i < 4; i++) {
        float inv = 1.f / l_i[i];
        int srow = qt * 64 + ty * 4 + i;
        float* yp = g_y + ((size_t)(b * SS + srow)) * DD + h * HD + tx * 4;
#pragma unroll
        for (int j = 0; j < 4; j++) yp[j] = o[i][j] * inv;
    }
}

// ---------------------------------------------------------------------------

extern "C" void kernel_launch(void* const* d_in, const int* in_sizes, int n_in,
                              void* d_out, int out_size) {
    const float* x      = (const float*)d_in[0];  // [2,2048,1024]
    const float* w_attn = (const float*)d_in[1];  // [1024,3072]
    const float* b_attn = (const float*)d_in[2];  // [3072]
    const float* w_proj = (const float*)d_in[3];  // [1024,1024]
    const float* b_proj = (const float*)d_in[4];  // [1024]
    float* out = (float*)d_out;

    cudaFuncSetAttribute(gemm_mma<N_QKV, true>,
                         cudaFuncAttributeMaxDynamicSharedMemorySize, GEMM_SMEM);
    cudaFuncSetAttribute(gemm_mma<DD, false>,
                         cudaFuncAttributeMaxDynamicSharedMemorySize, GEMM_SMEM);
    cudaFuncSetAttribute(attn_kernel,
                         cudaFuncAttributeMaxDynamicSharedMemorySize, (int)ATT_SMEM);

    // 1) QKV projection (tf32 mma.sync) + head-layout scatter
    gemm_mma<N_QKV, true><<<dim3(N_QKV / 128, MROWS / 128), 256, GEMM_SMEM>>>(
        x, w_attn, b_attn, nullptr);

    // 2) Causal flash attention (fp32)
    attn_kernel<<<dim3(SS / 64, BB * HH), 256, ATT_SMEM>>>();

    // 3) Output projection (tf32 mma.sync)
    gemm_mma<DD, false><<<dim3(DD / 128, MROWS / 128), 256, GEMM_SMEM>>>(
        nullptr, w_proj, b_proj, out);
}

// round 6
// speedup vs baseline: 2.3852x; 2.0750x over previous
#include <cuda_runtime.h>
#include <cstdint>

#define BB 2
#define SS 2048
#define DD 1024
#define HH 16
#define HD 64
#define MROWS (BB*SS)   // 4096
#define N_QKV (3*DD)    // 3072
#define KDIM 1024
#define NCHUNK (KDIM/32)

// ---------------- device scratch (no allocation allowed) -------------------
__device__ __align__(128) float g_q[BB*HH*SS*HD];   // [B,H,S,HD] fp32
__device__ __align__(128) float g_k[BB*HH*SS*HD];
__device__ __align__(128) float g_v[BB*HH*SS*HD];
__device__ __align__(128) float g_y[BB*SS*DD];      // [B,S,D] fp32
// fragment-major tf32 buffers (bits stored as float)
__device__ __align__(128) float g_xa[MROWS/128 * NCHUNK * 4096];  // A-frag of x
__device__ __align__(128) float g_ya[MROWS/128 * NCHUNK * 4096];  // A-frag of g_y
__device__ __align__(128) float g_wa[N_QKV/128 * NCHUNK * 4096];  // B-frag of w_attn
__device__ __align__(128) float g_wp[DD/128   * NCHUNK * 4096];   // B-frag of w_proj

__device__ __forceinline__ uint32_t f2tf(float x) {  // round-to-nearest tf32
    uint32_t r;
    asm("cvt.rna.tf32.f32 %0, %1;" : "=r"(r) : "f"(x));
    return r;
}
__device__ __forceinline__ float f2tff(float x) { return __uint_as_float(f2tf(x)); }

__device__ __forceinline__ uint32_t smem_u32(const void* p) {
    uint32_t a;
    asm("{ .reg .u64 t; cvta.to.shared.u64 t, %1; cvt.u32.u64 %0, t; }" : "=r"(a) : "l"(p));
    return a;
}

#define MMA_TF32(d, a, b) \
    asm volatile("mma.sync.aligned.m16n8k8.row.col.f32.tf32.tf32.f32 " \
        "{%0,%1,%2,%3}, {%4,%5,%6,%7}, {%8,%9}, {%0,%1,%2,%3};" \
        : "+f"((d)[0]), "+f"((d)[1]), "+f"((d)[2]), "+f"((d)[3]) \
        : "r"((a)[0]), "r"((a)[1]), "r"((a)[2]), "r"((a)[3]), \
          "r"((b)[0]), "r"((b)[1]))

#define CP16(dst, src) \
    asm volatile("cp.async.cg.shared.global [%0], [%1], 16;" :: "r"(dst), "l"(src) : "memory")
#define CP_COMMIT() asm volatile("cp.async.commit_group;" ::: "memory")
#define CP_WAIT2()  asm volatile("cp.async.wait_group 2;" ::: "memory")

// ---------------------------------------------------------------------------
// Pre-conversion kernels: fp32 -> tf32 fragment-major layouts.
// A-frag tile (128m x 32k): [mb 8][kb 4][lane 32 * reg 4]; global [mtile][chunk][4096]
// B-frag tile (128n x 32k): [nb 16][kb 4][lane 32 * reg 2]; global [ntile][chunk][4096]
// ---------------------------------------------------------------------------
__global__ __launch_bounds__(256) void conv_A(const float* __restrict__ X,
                                              float* __restrict__ out) {
    int idx = blockIdx.x * 256 + threadIdx.x;
    int lane = idx & 31;
    int kb = (idx >> 5) & 3;
    int mb = (idx >> 7) & 7;
    int chunk = (idx >> 10) & 31;
    int mtile = idx >> 15;
    int r = lane >> 2, c = lane & 3;
    int m = mtile * 128 + mb * 16;
    int k = chunk * 32 + kb * 8;
    float4 v;
    v.x = f2tff(X[(size_t)(m + r) * KDIM + k + c]);
    v.y = f2tff(X[(size_t)(m + r + 8) * KDIM + k + c]);
    v.z = f2tff(X[(size_t)(m + r) * KDIM + k + c + 4]);
    v.w = f2tff(X[(size_t)(m + r + 8) * KDIM + k + c + 4]);
    *(float4*)(out + (size_t)idx * 4) = v;
}

template<int N>
__global__ __launch_bounds__(256) void conv_B(const float* __restrict__ W,
                                              float* __restrict__ out) {
    int idx = blockIdx.x * 256 + threadIdx.x;
    int lane = idx & 31;
    int kb = (idx >> 5) & 3;
    int nb = (idx >> 7) & 15;
    int chunk = (idx >> 11) & 31;
    int ntile = idx >> 16;
    int n = ntile * 128 + nb * 8 + (lane >> 2);
    int k = chunk * 32 + kb * 8 + (lane & 3);
    float2 v;
    v.x = f2tff(W[(size_t)k * N + n]);
    v.y = f2tff(W[(size_t)(k + 4) * N + n]);
    *(float2*)(out + (size_t)idx * 2) = v;
}

// ---------------------------------------------------------------------------
// GEMM: cp.async 4-stage pipeline from preconverted frag buffers.
// CTA 128x128, 8 warps (4m x 2n), warp tile 32x64 (2x8 mma tiles).
// ---------------------------------------------------------------------------
#define GEMM_SMEM (4 * 32768)

template<int N, bool QKV>
__global__ __launch_bounds__(256) void gemm_cp(const float* __restrict__ Afrag,
                                               const float* __restrict__ Bfrag,
                                               const float* __restrict__ bias,
                                               float* __restrict__ Cout) {
    extern __shared__ float sm[];
    const uint32_t sb = smem_u32(sm);
    const int t = threadIdx.x;
    const int wid = t >> 5, lane = t & 31;
    const int warp_m = wid & 3, warp_n = wid >> 2;
    const int m0 = blockIdx.y * 128;
    const int n0 = blockIdx.x * 128;

    const float* Atile = Afrag + (size_t)blockIdx.y * (NCHUNK * 4096);
    const float* Btile = Bfrag + (size_t)blockIdx.x * (NCHUNK * 4096);

    float acc[2][8][4];
#pragma unroll
    for (int i = 0; i < 2; i++)
#pragma unroll
        for (int j = 0; j < 8; j++)
#pragma unroll
            for (int r = 0; r < 4; r++) acc[i][j][r] = 0.f;

#define ISSUE(c, s) do { \
        const float4* As_ = (const float4*)(Atile + (size_t)(c) * 4096) + t; \
        const float4* Bs_ = (const float4*)(Btile + (size_t)(c) * 4096) + t; \
        uint32_t d_ = sb + (s) * 32768u + (uint32_t)t * 16u; \
        _Pragma("unroll") \
        for (int q = 0; q < 4; q++) CP16(d_ + q * 4096u, As_ + q * 256); \
        _Pragma("unroll") \
        for (int q = 0; q < 4; q++) CP16(d_ + 16384u + q * 4096u, Bs_ + q * 256); \
    } while (0)

    ISSUE(0, 0); CP_COMMIT();
    ISSUE(1, 1); CP_COMMIT();
    ISSUE(2, 2); CP_COMMIT();

#pragma unroll 1
    for (int c = 0; c < NCHUNK; c++) {
        CP_WAIT2();
        __syncthreads();
        const float* Ab = sm + (c & 3) * 8192;
        const float* Bb = Ab + 4096;
#pragma unroll
        for (int kb = 0; kb < 4; kb++) {
            uint32_t af[2][4], bf[8][2];
#pragma unroll
            for (int i = 0; i < 2; i++) {
                float4 v = *(const float4*)(Ab + ((warp_m * 2 + i) * 4 + kb) * 128 + lane * 4);
                af[i][0] = __float_as_uint(v.x); af[i][1] = __float_as_uint(v.y);
                af[i][2] = __float_as_uint(v.z); af[i][3] = __float_as_uint(v.w);
            }
#pragma unroll
            for (int j = 0; j < 8; j++) {
                float2 v = *(const float2*)(Bb + ((warp_n * 8 + j) * 4 + kb) * 64 + lane * 2);
                bf[j][0] = __float_as_uint(v.x); bf[j][1] = __float_as_uint(v.y);
            }
#pragma unroll
            for (int i = 0; i < 2; i++)
#pragma unroll
                for (int j = 0; j < 8; j++)
                    MMA_TF32(acc[i][j], af[i], bf[j]);
        }
        if (c + 3 < NCHUNK) ISSUE(c + 3, (c + 3) & 3);
        CP_COMMIT();
    }
#undef ISSUE

    // Epilogue
    const int r0 = lane >> 2;
    const int cp = (lane & 3) * 2;
#pragma unroll
    for (int i = 0; i < 2; i++) {
        const int mbase = m0 + warp_m * 32 + i * 16;
#pragma unroll
        for (int j = 0; j < 8; j++) {
            const int n = n0 + warp_n * 64 + j * 8 + cp;
            const float bx = bias[n], by = bias[n + 1];
            float2 v01 = make_float2(acc[i][j][0] + bx, acc[i][j][1] + by);
            float2 v23 = make_float2(acc[i][j][2] + bx, acc[i][j][3] + by);
            if (QKV) {
                const int which = n >> 10;
                const int h = (n >> 6) & 15;
                const int d = n & 63;
                float* dst = (which == 0) ? g_q : (which == 1) ? g_k : g_v;
                int m1 = mbase + r0;
                int m2 = m1 + 8;
                *(float2*)(dst + ((((size_t)(m1 >> 11) * HH + h) * SS + (m1 & 2047)) * HD + d)) = v01;
                *(float2*)(dst + ((((size_t)(m2 >> 11) * HH + h) * SS + (m2 & 2047)) * HD + d)) = v23;
            } else {
                *(float2*)(Cout + (size_t)(mbase + r0) * DD + n) = v01;
                *(float2*)(Cout + (size_t)(mbase + r0 + 8) * DD + n) = v23;
            }
        }
    }
}

// ---------------------------------------------------------------------------
// Flash attention with m16n8k8 tf32 mma. 128 threads = 4 warps; warp w owns
// q-rows [w*16, w*16+16) of a 64-row tile. Q persistent A-frags in regs.
// K/V staged to B-frag smem (lane-rotated scatter, <=2-way conflicts).
// P round-trips through warp-private A-frag smem (__syncwarp only).
// smem: Qa[4096] Kb[4096] Vb[4096] Pa[4096] floats = 64KB.
// ---------------------------------------------------------------------------
#define AQ 0
#define AK 4096
#define AV 8192
#define AP 12288
#define ATT_SMEM (16384 * 4)

__global__ __launch_bounds__(128) void attn_mma() {
    extern __shared__ float sh[];
    const int t = threadIdx.x;
    const int w = t >> 5, l = t & 31;
    const int qt = blockIdx.x;   // 64-row q tile
    const int bh = blockIdx.y;   // b*H + h

    const float* qg = g_q + (size_t)bh * (SS * HD) + (size_t)qt * 64 * HD;
    const float* kg = g_k + (size_t)bh * (SS * HD);
    const float* vg = g_v + (size_t)bh * (SS * HD);

    // ---- stage Q -> A-frag (once) ----
    {
        int r = t >> 1, ch = (t & 1) * 32;
#pragma unroll
        for (int q = 0; q < 8; q++) {
            float4 v = *(const float4*)(qg + r * HD + ch + q * 4);
            float a[4] = {v.x, v.y, v.z, v.w};
#pragma unroll
            for (int m = 0; m < 4; m++) {
                int c = ch + q * 4 + m;
                int mb = r >> 4, kb = c >> 3;
                int lp = ((r & 7) << 2) | (c & 3);
                int rg = (((r & 15) >= 8) ? 1 : 0) + (((c & 7) >= 4) ? 2 : 0);
                sh[AQ + (mb * 8 + kb) * 128 + lp * 4 + rg] = f2tff(a[m]);
            }
        }
    }
    __syncthreads();

    uint32_t qa[8][4];
#pragma unroll
    for (int kb = 0; kb < 8; kb++) {
        float4 v = *(const float4*)&sh[AQ + (w * 8 + kb) * 128 + l * 4];
        qa[kb][0] = __float_as_uint(v.x); qa[kb][1] = __float_as_uint(v.y);
        qa[kb][2] = __float_as_uint(v.z); qa[kb][3] = __float_as_uint(v.w);
    }

    float O[8][4];
#pragma unroll
    for (int j = 0; j < 8; j++)
#pragma unroll
        for (int r = 0; r < 4; r++) O[j][r] = 0.f;
    float m1 = -1e30f, m2 = -1e30f, l1 = 0.f, l2 = 0.f;

    // K/V staging map: warp-friendly row assignment + lane-rotated scalar order
    const int w2 = (t >> 5) & 1;
    const int half = t >> 6;
    const int s_row = w2 * 32 + ((l & 7) << 2) + (l >> 3);
    const int dbase = half * 32;

    for (int kt = 0; kt <= qt; kt++) {
        __syncthreads();
        {
            const float* krow = kg + (size_t)(kt * 64 + s_row) * HD + dbase;
            const float* vrow = vg + (size_t)(kt * 64 + s_row) * HD + dbase;
#pragma unroll
            for (int q = 0; q < 8; q++) {
                float4 kv = *(const float4*)(krow + q * 4);
                float4 vv = *(const float4*)(vrow + q * 4);
                float ka[4] = {kv.x, kv.y, kv.z, kv.w};
                float va[4] = {vv.x, vv.y, vv.z, vv.w};
#pragma unroll
                for (int m = 0; m < 4; m++) {
                    int rot = (m + l) & 3;
                    int dd = dbase + q * 4 + rot;
                    // K slot: B(k=d, n=s)
                    int nb = s_row >> 3, kb = dd >> 3;
                    int lp = ((s_row & 7) << 2) | (dd & 3);
                    int rg = (dd & 7) >> 2;
                    sh[AK + (nb * 8 + kb) * 64 + lp * 2 + rg] = f2tff(ka[rot]);
                    // V slot: B(k=s, n=d)
                    int nb2 = dd >> 3, kb2 = s_row >> 3;
                    int lp2 = ((dd & 7) << 2) | (s_row & 3);
                    int rg2 = (s_row & 7) >> 2;
                    sh[AV + (nb2 * 8 + kb2) * 64 + lp2 * 2 + rg2] = f2tff(va[rot]);
                }
            }
        }
        __syncthreads();

        // ---- S = Q @ K^T ----
        float S[8][4];
#pragma unroll
        for (int j = 0; j < 8; j++) {
#pragma unroll
            for (int r = 0; r < 4; r++) S[j][r] = 0.f;
#pragma unroll
            for (int kb = 0; kb < 8; kb++) {
                float2 bv = *(const float2*)&sh[AK + (j * 8 + kb) * 64 + l * 2];
                uint32_t bf[2] = {__float_as_uint(bv.x), __float_as_uint(bv.y)};
                MMA_TF32(S[j], qa[kb], bf);
            }
        }

        const float sc = 0.125f;
        const int qr1 = w * 16 + (l >> 2);
        const int qr2 = qr1 + 8;
        if (kt == qt) {
#pragma unroll
            for (int j = 0; j < 8; j++) {
                int c0 = j * 8 + (l & 3) * 2, c1 = c0 + 1;
                S[j][0] = (c0 <= qr1) ? S[j][0] * sc : -1e30f;
                S[j][1] = (c1 <= qr1) ? S[j][1] * sc : -1e30f;
                S[j][2] = (c0 <= qr2) ? S[j][2] * sc : -1e30f;
                S[j][3] = (c1 <= qr2) ? S[j][3] * sc : -1e30f;
            }
        } else {
#pragma unroll
            for (int j = 0; j < 8; j++)
#pragma unroll
                for (int r = 0; r < 4; r++) S[j][r] *= sc;
        }

        // ---- online softmax (rows qr1, qr2 per lane; quad reduce) ----
        float rm1 = -1e30f, rm2 = -1e30f;
#pragma unroll
        for (int j = 0; j < 8; j++) {
            rm1 = fmaxf(rm1, fmaxf(S[j][0], S[j][1]));
            rm2 = fmaxf(rm2, fmaxf(S[j][2], S[j][3]));
        }
        rm1 = fmaxf(rm1, __shfl_xor_sync(0xffffffffu, rm1, 1));
        rm1 = fmaxf(rm1, __shfl_xor_sync(0xffffffffu, rm1, 2));
        rm2 = fmaxf(rm2, __shfl_xor_sync(0xffffffffu, rm2, 1));
        rm2 = fmaxf(rm2, __shfl_xor_sync(0xffffffffu, rm2, 2));
        float mn1 = fmaxf(m1, rm1), mn2 = fmaxf(m2, rm2);
        float fi1 = __expf(m1 - mn1), fi2 = __expf(m2 - mn2);
        m1 = mn1; m2 = mn2;
        float rs1 = 0.f, rs2 = 0.f;
#pragma unroll
        for (int j = 0; j < 8; j++) {
            S[j][0] = __expf(S[j][0] - m1);
            S[j][1] = __expf(S[j][1] - m1);
            S[j][2] = __expf(S[j][2] - m2);
            S[j][3] = __expf(S[j][3] - m2);
            rs1 += S[j][0] + S[j][1];
            rs2 += S[j][2] + S[j][3];
        }
        rs1 += __shfl_xor_sync(0xffffffffu, rs1, 1);
        rs1 += __shfl_xor_sync(0xffffffffu, rs1, 2);
        rs2 += __shfl_xor_sync(0xffffffffu, rs2, 1);
        rs2 += __shfl_xor_sync(0xffffffffu, rs2, 2);
        l1 = l1 * fi1 + rs1;
        l2 = l2 * fi2 + rs2;
#pragma unroll
        for (int j = 0; j < 8; j++) {
            O[j][0] *= fi1; O[j][1] *= fi1;
            O[j][2] *= fi2; O[j][3] *= fi2;
        }

        // ---- store P (C-frag) -> A-frag smem, rotated order ----
        {
            const int r1 = l >> 2;
            const int c03 = ((l & 3) * 2) & 3;          // c0 & 3
            const int rotb = (l >> 1) & 3;
#pragma unroll
            for (int j = 0; j < 8; j++) {
                int c0 = j * 8 + (l & 3) * 2;
                int rgc = ((c0 & 7) >= 4) ? 2 : 0;
                float* base = &sh[AP + (w * 8 + j) * 128 + (r1 * 4 + c03) * 4 + rgc];
                float vals[4] = {S[j][0], S[j][2], S[j][1], S[j][3]};  // offsets 0,1,4,5
#pragma unroll
                for (int m = 0; m < 4; m++) {
                    int oi = (m + rotb) & 3;
                    int off = (oi & 1) + (oi >> 1) * 4;
                    base[off] = f2tff(vals[oi]);
                }
            }
        }
        __syncwarp();

        // ---- O += P @ V ----
        {
            uint32_t pa[8][4];
#pragma unroll
            for (int kb = 0; kb < 8; kb++) {
                float4 v = *(const float4*)&sh[AP + (w * 8 + kb) * 128 + l * 4];
                pa[kb][0] = __float_as_uint(v.x); pa[kb][1] = __float_as_uint(v.y);
                pa[kb][2] = __float_as_uint(v.z); pa[kb][3] = __float_as_uint(v.w);
            }
#pragma unroll
            for (int j = 0; j < 8; j++)
#pragma unroll
                for (int kb = 0; kb < 8; kb++) {
                    float2 bv = *(const float2*)&sh[AV + (j * 8 + kb) * 64 + l * 2];
                    uint32_t bf[2] = {__float_as_uint(bv.x), __float_as_uint(bv.y)};
                    MMA_TF32(O[j], pa[kb], bf);
                }
        }
    }

    // ---- epilogue: O /= l, write [B,S,D] ----
    const int b = bh >> 4, h = bh & 15;
    const float inv1 = 1.f / l1, inv2 = 1.f / l2;
    const int row1 = qt * 64 + w * 16 + (l >> 2);
    const int row2 = row1 + 8;
#pragma unroll
    for (int j = 0; j < 8; j++) {
        int c0 = j * 8 + (l & 3) * 2;
        *(float2*)(g_y + ((size_t)(b * SS + row1)) * DD + h * HD + c0) =
            make_float2(O[j][0] * inv1, O[j][1] * inv1);
        *(float2*)(g_y + ((size_t)(b * SS + row2)) * DD + h * HD + c0) =
            make_float2(O[j][2] * inv2, O[j][3] * inv2);
    }
}

// ---------------------------------------------------------------------------

extern "C" void kernel_launch(void* const* d_in, const int* in_sizes, int n_in,
                              void* d_out, int out_size) {
    const float* x      = (const float*)d_in[0];  // [2,2048,1024]
    const float* w_attn = (const float*)d_in[1];  // [1024,3072]
    const float* b_attn = (const float*)d_in[2];  // [3072]
    const float* w_proj = (const float*)d_in[3];  // [1024,1024]
    const float* b_proj = (const float*)d_in[4];  // [1024]
    float* out = (float*)d_out;

    float* xa; cudaGetSymbolAddress((void**)&xa, g_xa);
    float* ya; cudaGetSymbolAddress((void**)&ya, g_ya);
    float* wa; cudaGetSymbolAddress((void**)&wa, g_wa);
    float* wp; cudaGetSymbolAddress((void**)&wp, g_wp);
    float* yy; cudaGetSymbolAddress((void**)&yy, g_y);

    cudaFuncSetAttribute(gemm_cp<N_QKV, true>,
                         cudaFuncAttributeMaxDynamicSharedMemorySize, GEMM_SMEM);
    cudaFuncSetAttribute(gemm_cp<DD, false>,
                         cudaFuncAttributeMaxDynamicSharedMemorySize, GEMM_SMEM);
    cudaFuncSetAttribute(attn_mma,
                         cudaFuncAttributeMaxDynamicSharedMemorySize, (int)ATT_SMEM);

    // 0) preconvert weights + x to tf32 fragment layouts
    conv_A<<<(MROWS/128) * NCHUNK * 32 / 8, 256>>>(x, xa);        // 4096 blocks
    conv_B<N_QKV><<<(N_QKV/128) * NCHUNK * 64 / 8, 256>>>(w_attn, wa);
    conv_B<DD><<<(DD/128) * NCHUNK * 64 / 8, 256>>>(w_proj, wp);

    // 1) QKV projection (tensor cores, cp.async pipeline)
    gemm_cp<N_QKV, true><<<dim3(N_QKV / 128, MROWS / 128), 256, GEMM_SMEM>>>(
        xa, wa, b_attn, nullptr);

    // 2) causal flash attention (tensor cores)
    attn_mma<<<dim3(SS / 64, BB * HH), 128, ATT_SMEM>>>();

    // 3) convert attention output to A-frag layout
    conv_A<<<(MROWS/128) * NCHUNK * 32 / 8, 256>>>(yy, ya);

    // 4) output projection
    gemm_cp<DD, false><<<dim3(DD / 128, MROWS / 128), 256, GEMM_SMEM>>>(
        ya, wp, b_proj, out);
}

// round 7
// speedup vs baseline: 3.1256x; 1.3104x over previous
#include <cuda_runtime.h>
#include <cstdint>

#define BB 2
#define SS 2048
#define DD 1024
#define HH 16
#define HD 64
#define MROWS (BB*SS)   // 4096
#define N_QKV (3*DD)    // 3072
#define KDIM 1024
#define NCHUNK (KDIM/32)

// ---------------- device scratch (no allocation allowed) -------------------
__device__ __align__(128) float g_q[BB*HH*SS*HD];   // [B,H,S,HD] fp32
__device__ __align__(128) float g_k[BB*HH*SS*HD];
__device__ __align__(128) float g_v[BB*HH*SS*HD];
__device__ __align__(128) float g_y[BB*SS*DD];      // [B,S,D] fp32
// fragment-major tf32 buffers (bits stored as float)
__device__ __align__(128) float g_xa[MROWS/128 * NCHUNK * 4096];  // A-frag of x
__device__ __align__(128) float g_ya[MROWS/128 * NCHUNK * 4096];  // A-frag of g_y
__device__ __align__(128) float g_wa[N_QKV/128 * NCHUNK * 4096];  // B-frag of w_attn
__device__ __align__(128) float g_wp[DD/128   * NCHUNK * 4096];   // B-frag of w_proj
// attention frag buffers: per bh stride 131072 floats
__device__ __align__(128) float g_qf[32 * 131072];  // A-frag of Q [bh][mb128][kb8][128]
__device__ __align__(128) float g_kf[32 * 131072];  // B-frag of K [bh][sb256][kb8][64]
__device__ __align__(128) float g_vf[32 * 131072];  // B-frag of V [bh][kt32][nb8][kb8][64]

__device__ __forceinline__ uint32_t f2tf(float x) {  // round-to-nearest tf32
    uint32_t r;
    asm("cvt.rna.tf32.f32 %0, %1;" : "=r"(r) : "f"(x));
    return r;
}
__device__ __forceinline__ float f2tff(float x) { return __uint_as_float(f2tf(x)); }

__device__ __forceinline__ uint32_t smem_u32(const void* p) {
    uint32_t a;
    asm("{ .reg .u64 t; cvta.to.shared.u64 t, %1; cvt.u32.u64 %0, t; }" : "=r"(a) : "l"(p));
    return a;
}

#define MMA_TF32(d, a, b) \
    asm volatile("mma.sync.aligned.m16n8k8.row.col.f32.tf32.tf32.f32 " \
        "{%0,%1,%2,%3}, {%4,%5,%6,%7}, {%8,%9}, {%0,%1,%2,%3};" \
        : "+f"((d)[0]), "+f"((d)[1]), "+f"((d)[2]), "+f"((d)[3]) \
        : "r"((a)[0]), "r"((a)[1]), "r"((a)[2]), "r"((a)[3]), \
          "r"((b)[0]), "r"((b)[1]))

#define CP16(dst, src) \
    asm volatile("cp.async.cg.shared.global [%0], [%1], 16;" :: "r"(dst), "l"(src) : "memory")
#define CP_COMMIT() asm volatile("cp.async.commit_group;" ::: "memory")
#define CP_WAIT2()  asm volatile("cp.async.wait_group 2;" ::: "memory")
#define CP_WAIT1()  asm volatile("cp.async.wait_group 1;" ::: "memory")

// ---------------------------------------------------------------------------
// Pre-conversion kernels: fp32 -> tf32 fragment-major layouts.
// ---------------------------------------------------------------------------
__global__ __launch_bounds__(256) void conv_A(const float* __restrict__ X,
                                              float* __restrict__ out) {
    int idx = blockIdx.x * 256 + threadIdx.x;
    int lane = idx & 31;
    int kb = (idx >> 5) & 3;
    int mb = (idx >> 7) & 7;
    int chunk = (idx >> 10) & 31;
    int mtile = idx >> 15;
    int r = lane >> 2, c = lane & 3;
    int m = mtile * 128 + mb * 16;
    int k = chunk * 32 + kb * 8;
    float4 v;
    v.x = f2tff(X[(size_t)(m + r) * KDIM + k + c]);
    v.y = f2tff(X[(size_t)(m + r + 8) * KDIM + k + c]);
    v.z = f2tff(X[(size_t)(m + r) * KDIM + k + c + 4]);
    v.w = f2tff(X[(size_t)(m + r + 8) * KDIM + k + c + 4]);
    *(float4*)(out + (size_t)idx * 4) = v;
}

template<int N>
__global__ __launch_bounds__(256) void conv_B(const float* __restrict__ W,
                                              float* __restrict__ out) {
    int idx = blockIdx.x * 256 + threadIdx.x;
    int lane = idx & 31;
    int kb = (idx >> 5) & 3;
    int nb = (idx >> 7) & 15;
    int chunk = (idx >> 11) & 31;
    int ntile = idx >> 16;
    int n = ntile * 128 + nb * 8 + (lane >> 2);
    int k = chunk * 32 + kb * 8 + (lane & 3);
    float2 v;
    v.x = f2tff(W[(size_t)k * N + n]);
    v.y = f2tff(W[(size_t)(k + 4) * N + n]);
    *(float2*)(out + (size_t)idx * 2) = v;
}

// Q [bh][s][d] -> A-frag [bh][mb 128][kb 8][lane32*reg4]
__global__ __launch_bounds__(256) void conv_Qf() {
    int idx = blockIdx.x * 256 + threadIdx.x;   // 1,048,576 threads
    int lane = idx & 31;
    int kb = (idx >> 5) & 7;
    int mb = (idx >> 8) & 127;
    int bh = idx >> 15;
    int r = lane >> 2, c = lane & 3;
    const float* Q = g_q + (size_t)bh * (SS * HD);
    int s = mb * 16, d = kb * 8;
    float4 v;
    v.x = f2tff(Q[(size_t)(s + r) * HD + d + c]);
    v.y = f2tff(Q[(size_t)(s + r + 8) * HD + d + c]);
    v.z = f2tff(Q[(size_t)(s + r) * HD + d + c + 4]);
    v.w = f2tff(Q[(size_t)(s + r + 8) * HD + d + c + 4]);
    *(float4*)(g_qf + (size_t)idx * 4) = v;
}

// K [bh][s][d] -> B-frag (n=s, k=d): [bh][sb 256][kb 8][lane32*reg2]
__global__ __launch_bounds__(256) void conv_Kf() {
    int idx = blockIdx.x * 256 + threadIdx.x;   // 2,097,152 threads
    int lane = idx & 31;
    int kb = (idx >> 5) & 7;
    int sb = (idx >> 8) & 255;
    int bh = idx >> 16;
    int s = sb * 8 + (lane >> 2);
    int d = kb * 8 + (lane & 3);
    const float* K = g_k + (size_t)bh * (SS * HD);
    float2 v;
    v.x = f2tff(K[(size_t)s * HD + d]);
    v.y = f2tff(K[(size_t)s * HD + d + 4]);
    *(float2*)(g_kf + (size_t)idx * 2) = v;
}

// V [bh][s][d] -> B-frag (n=d, k=s): [bh][kt 32][nb 8][kb 8][lane32*reg2]
__global__ __launch_bounds__(256) void conv_Vf() {
    int idx = blockIdx.x * 256 + threadIdx.x;   // 2,097,152 threads
    int lane = idx & 31;
    int kb = (idx >> 5) & 7;
    int nb = (idx >> 8) & 7;
    int kt = (idx >> 11) & 31;
    int bh = idx >> 16;
    int d = nb * 8 + (lane >> 2);
    int s = kt * 64 + kb * 8 + (lane & 3);
    const float* V = g_v + (size_t)bh * (SS * HD);
    float2 v;
    v.x = f2tff(V[(size_t)s * HD + d]);
    v.y = f2tff(V[(size_t)(s + 4) * HD + d]);
    *(float2*)(g_vf + (size_t)idx * 2) = v;
}

// ---------------------------------------------------------------------------
// GEMM: cp.async 4-stage pipeline from preconverted frag buffers. (unchanged)
// ---------------------------------------------------------------------------
#define GEMM_SMEM (4 * 32768)

template<int N, bool QKV>
__global__ __launch_bounds__(256) void gemm_cp(const float* __restrict__ Afrag,
                                               const float* __restrict__ Bfrag,
                                               const float* __restrict__ bias,
                                               float* __restrict__ Cout) {
    extern __shared__ float sm[];
    const uint32_t sb = smem_u32(sm);
    const int t = threadIdx.x;
    const int wid = t >> 5, lane = t & 31;
    const int warp_m = wid & 3, warp_n = wid >> 2;
    const int m0 = blockIdx.y * 128;
    const int n0 = blockIdx.x * 128;

    const float* Atile = Afrag + (size_t)blockIdx.y * (NCHUNK * 4096);
    const float* Btile = Bfrag + (size_t)blockIdx.x * (NCHUNK * 4096);

    float acc[2][8][4];
#pragma unroll
    for (int i = 0; i < 2; i++)
#pragma unroll
        for (int j = 0; j < 8; j++)
#pragma unroll
            for (int r = 0; r < 4; r++) acc[i][j][r] = 0.f;

#define ISSUE(c, s) do { \
        const float4* As_ = (const float4*)(Atile + (size_t)(c) * 4096) + t; \
        const float4* Bs_ = (const float4*)(Btile + (size_t)(c) * 4096) + t; \
        uint32_t d_ = sb + (s) * 32768u + (uint32_t)t * 16u; \
        _Pragma("unroll") \
        for (int q = 0; q < 4; q++) CP16(d_ + q * 4096u, As_ + q * 256); \
        _Pragma("unroll") \
        for (int q = 0; q < 4; q++) CP16(d_ + 16384u + q * 4096u, Bs_ + q * 256); \
    } while (0)

    ISSUE(0, 0); CP_COMMIT();
    ISSUE(1, 1); CP_COMMIT();
    ISSUE(2, 2); CP_COMMIT();

#pragma unroll 1
    for (int c = 0; c < NCHUNK; c++) {
        CP_WAIT2();
        __syncthreads();
        const float* Ab = sm + (c & 3) * 8192;
        const float* Bb = Ab + 4096;
#pragma unroll
        for (int kb = 0; kb < 4; kb++) {
            uint32_t af[2][4], bf[8][2];
#pragma unroll
            for (int i = 0; i < 2; i++) {
                float4 v = *(const float4*)(Ab + ((warp_m * 2 + i) * 4 + kb) * 128 + lane * 4);
                af[i][0] = __float_as_uint(v.x); af[i][1] = __float_as_uint(v.y);
                af[i][2] = __float_as_uint(v.z); af[i][3] = __float_as_uint(v.w);
            }
#pragma unroll
            for (int j = 0; j < 8; j++) {
                float2 v = *(const float2*)(Bb + ((warp_n * 8 + j) * 4 + kb) * 64 + lane * 2);
                bf[j][0] = __float_as_uint(v.x); bf[j][1] = __float_as_uint(v.y);
            }
#pragma unroll
            for (int i = 0; i < 2; i++)
#pragma unroll
                for (int j = 0; j < 8; j++)
                    MMA_TF32(acc[i][j], af[i], bf[j]);
        }
        if (c + 3 < NCHUNK) ISSUE(c + 3, (c + 3) & 3);
        CP_COMMIT();
    }
#undef ISSUE

    // Epilogue
    const int r0 = lane >> 2;
    const int cp = (lane & 3) * 2;
#pragma unroll
    for (int i = 0; i < 2; i++) {
        const int mbase = m0 + warp_m * 32 + i * 16;
#pragma unroll
        for (int j = 0; j < 8; j++) {
            const int n = n0 + warp_n * 64 + j * 8 + cp;
            const float bx = bias[n], by = bias[n + 1];
            float2 v01 = make_float2(acc[i][j][0] + bx, acc[i][j][1] + by);
            float2 v23 = make_float2(acc[i][j][2] + bx, acc[i][j][3] + by);
            if (QKV) {
                const int which = n >> 10;
                const int h = (n >> 6) & 15;
                const int d = n & 63;
                float* dst = (which == 0) ? g_q : (which == 1) ? g_k : g_v;
                int m1 = mbase + r0;
                int m2 = m1 + 8;
                *(float2*)(dst + ((((size_t)(m1 >> 11) * HH + h) * SS + (m1 & 2047)) * HD + d)) = v01;
                *(float2*)(dst + ((((size_t)(m2 >> 11) * HH + h) * SS + (m2 & 2047)) * HD + d)) = v23;
            } else {
                *(float2*)(Cout + (size_t)(mbase + r0) * DD + n) = v01;
                *(float2*)(Cout + (size_t)(mbase + r0 + 8) * DD + n) = v23;
            }
        }
    }
}

// ---------------------------------------------------------------------------
// Flash attention v2: 256 threads (8 warps), q-tile 128 rows (warp w owns 16),
// K/V 64-key tiles cp.async'd from preconverted frag buffers, double buffered.
// smem: KV[2][8192 floats] + P[8192 floats] = 96KB.
// ---------------------------------------------------------------------------
#define ATT2_SMEM (3 * 32768)

__global__ __launch_bounds__(256, 2) void attn_mma2() {
    extern __shared__ float sh[];
    const uint32_t sbase = smem_u32(sh);
    const int t = threadIdx.x;
    const int w = t >> 5, l = t & 31;
    const int qt = gridDim.x - 1 - blockIdx.x;   // heavy tiles first
    const int bh = blockIdx.y;

    const float* Qf  = g_qf + (size_t)bh * 131072 + (size_t)(qt * 8 + w) * 1024;
    const float* Kbh = g_kf + (size_t)bh * 131072;
    const float* Vbh = g_vf + (size_t)bh * 131072;

    // Q fragments (persistent, direct LDG from frag buffer)
    uint32_t qa[8][4];
#pragma unroll
    for (int kb = 0; kb < 8; kb++) {
        float4 v = *(const float4*)(Qf + kb * 128 + l * 4);
        qa[kb][0] = __float_as_uint(v.x); qa[kb][1] = __float_as_uint(v.y);
        qa[kb][2] = __float_as_uint(v.z); qa[kb][3] = __float_as_uint(v.w);
    }

    float O[8][4];
#pragma unroll
    for (int j = 0; j < 8; j++)
#pragma unroll
        for (int r = 0; r < 4; r++) O[j][r] = 0.f;
    float m1 = -1e30f, m2 = -1e30f, l1 = 0.f, l2 = 0.f;

    const int ntiles = 2 * qt + 2;
    const int qrow_lo = qt * 128 + w * 16;     // warp's smallest q row
    const int qr1 = qrow_lo + (l >> 2);
    const int qr2 = qr1 + 8;

#define AISSUE(kt) do { \
        if ((kt) < ntiles) { \
            const float4* ks_ = (const float4*)(Kbh + (size_t)(kt) * 4096) + t; \
            const float4* vs_ = (const float4*)(Vbh + (size_t)(kt) * 4096) + t; \
            uint32_t db_ = sbase + ((kt) & 1) * 32768u + (uint32_t)t * 16u; \
            _Pragma("unroll") \
            for (int q = 0; q < 4; q++) CP16(db_ + q * 4096u, ks_ + q * 256); \
            _Pragma("unroll") \
            for (int q = 0; q < 4; q++) CP16(db_ + 16384u + q * 4096u, vs_ + q * 256); \
        } } while (0)

    AISSUE(0); CP_COMMIT();
    AISSUE(1); CP_COMMIT();

#pragma unroll 1
    for (int kt = 0; kt < ntiles; kt++) {
        CP_WAIT1();
        __syncthreads();

        const bool active = (kt * 64) <= (qrow_lo + 15);
        if (active) {
            const float* Kb = sh + (kt & 1) * 8192;
            const float* Vb = Kb + 4096;

            // ---- S = Q @ K^T ----
            float S[8][4];
#pragma unroll
            for (int j = 0; j < 8; j++) {
#pragma unroll
                for (int r = 0; r < 4; r++) S[j][r] = 0.f;
#pragma unroll
                for (int kb = 0; kb < 8; kb++) {
                    float2 bv = *(const float2*)&Kb[(j * 8 + kb) * 64 + l * 2];
                    uint32_t bf[2] = {__float_as_uint(bv.x), __float_as_uint(bv.y)};
                    MMA_TF32(S[j], qa[kb], bf);
                }
            }

            const float sc = 0.125f;
            if (kt * 64 + 63 > qrow_lo) {   // diagonal tile: mask
#pragma unroll
                for (int j = 0; j < 8; j++) {
                    int c0 = kt * 64 + j * 8 + (l & 3) * 2, c1 = c0 + 1;
                    S[j][0] = (c0 <= qr1) ? S[j][0] * sc : -1e30f;
                    S[j][1] = (c1 <= qr1) ? S[j][1] * sc : -1e30f;
                    S[j][2] = (c0 <= qr2) ? S[j][2] * sc : -1e30f;
                    S[j][3] = (c1 <= qr2) ? S[j][3] * sc : -1e30f;
                }
            } else {
#pragma unroll
                for (int j = 0; j < 8; j++)
#pragma unroll
                    for (int r = 0; r < 4; r++) S[j][r] *= sc;
            }

            // ---- online softmax (2 rows per lane, quad reduce) ----
            float rm1 = -1e30f, rm2 = -1e30f;
#pragma unroll
            for (int j = 0; j < 8; j++) {
                rm1 = fmaxf(rm1, fmaxf(S[j][0], S[j][1]));
                rm2 = fmaxf(rm2, fmaxf(S[j][2], S[j][3]));
            }
            rm1 = fmaxf(rm1, __shfl_xor_sync(0xffffffffu, rm1, 1));
            rm1 = fmaxf(rm1, __shfl_xor_sync(0xffffffffu, rm1, 2));
            rm2 = fmaxf(rm2, __shfl_xor_sync(0xffffffffu, rm2, 1));
            rm2 = fmaxf(rm2, __shfl_xor_sync(0xffffffffu, rm2, 2));
            float mn1 = fmaxf(m1, rm1), mn2 = fmaxf(m2, rm2);
            float fi1 = __expf(m1 - mn1), fi2 = __expf(m2 - mn2);
            m1 = mn1; m2 = mn2;
            float rs1 = 0.f, rs2 = 0.f;
#pragma unroll
            for (int j = 0; j < 8; j++) {
                S[j][0] = __expf(S[j][0] - m1);
                S[j][1] = __expf(S[j][1] - m1);
                S[j][2] = __expf(S[j][2] - m2);
                S[j][3] = __expf(S[j][3] - m2);
                rs1 += S[j][0] + S[j][1];
                rs2 += S[j][2] + S[j][3];
            }
            rs1 += __shfl_xor_sync(0xffffffffu, rs1, 1);
            rs1 += __shfl_xor_sync(0xffffffffu, rs1, 2);
            rs2 += __shfl_xor_sync(0xffffffffu, rs2, 1);
            rs2 += __shfl_xor_sync(0xffffffffu, rs2, 2);
            l1 = l1 * fi1 + rs1;
            l2 = l2 * fi2 + rs2;
#pragma unroll
            for (int j = 0; j < 8; j++) {
                O[j][0] *= fi1; O[j][1] *= fi1;
                O[j][2] *= fi2; O[j][3] *= fi2;
            }

            // ---- store P (C-frag) -> warp-private A-frag smem ----
            {
                float* Pw = sh + 16384;
                const int r1 = l >> 2;
                const int c03 = ((l & 3) * 2) & 3;
                const int rotb = (l >> 1) & 3;
#pragma unroll
                for (int j = 0; j < 8; j++) {
                    int c0j = (l & 3) * 2;
                    int rgc = ((c0j & 7) >= 4) ? 2 : 0;
                    float* base = &Pw[(w * 8 + j) * 128 + (r1 * 4 + c03) * 4 + rgc];
                    float vals[4] = {S[j][0], S[j][2], S[j][1], S[j][3]};
#pragma unroll
                    for (int m = 0; m < 4; m++) {
                        int oi = (m + rotb) & 3;
                        int off = (oi & 1) + (oi >> 1) * 4;
                        base[off] = f2tff(vals[oi]);
                    }
                }
            }
            __syncwarp();

            // ---- O += P @ V ----
            {
                const float* Pw = sh + 16384;
                uint32_t pa[8][4];
#pragma unroll
                for (int kb = 0; kb < 8; kb++) {
                    float4 v = *(const float4*)&Pw[(w * 8 + kb) * 128 + l * 4];
                    pa[kb][0] = __float_as_uint(v.x); pa[kb][1] = __float_as_uint(v.y);
                    pa[kb][2] = __float_as_uint(v.z); pa[kb][3] = __float_as_uint(v.w);
                }
#pragma unroll
                for (int j = 0; j < 8; j++)
#pragma unroll
                    for (int kb = 0; kb < 8; kb++) {
                        float2 bv = *(const float2*)&Vb[(j * 8 + kb) * 64 + l * 2];
                        uint32_t bf[2] = {__float_as_uint(bv.x), __float_as_uint(bv.y)};
                        MMA_TF32(O[j], pa[kb], bf);
                    }
            }
        }

        __syncthreads();
        AISSUE(kt + 2);
        CP_COMMIT();
    }
#undef AISSUE

    // ---- epilogue: O /= l, write [B,S,D] ----
    const int b = bh >> 4, h = bh & 15;
    const float inv1 = 1.f / l1, inv2 = 1.f / l2;
    const int row1 = qr1, row2 = qr2;
#pragma unroll
    for (int j = 0; j < 8; j++) {
        int c0 = j * 8 + (l & 3) * 2;
        *(float2*)(g_y + ((size_t)(b * SS + row1)) * DD + h * HD + c0) =
            make_float2(O[j][0] * inv1, O[j][1] * inv1);
        *(float2*)(g_y + ((size_t)(b * SS + row2)) * DD + h * HD + c0) =
            make_float2(O[j][2] * inv2, O[j][3] * inv2);
    }
}

// ---------------------------------------------------------------------------

extern "C" void kernel_launch(void* const* d_in, const int* in_sizes, int n_in,
                              void* d_out, int out_size) {
    const float* x      = (const float*)d_in[0];  // [2,2048,1024]
    const float* w_attn = (const float*)d_in[1];  // [1024,3072]
    const float* b_attn = (const float*)d_in[2];  // [3072]
    const float* w_proj = (const float*)d_in[3];  // [1024,1024]
    const float* b_proj = (const float*)d_in[4];  // [1024]
    float* out = (float*)d_out;

    float* xa; cudaGetSymbolAddress((void**)&xa, g_xa);
    float* ya; cudaGetSymbolAddress((void**)&ya, g_ya);
    float* wa; cudaGetSymbolAddress((void**)&wa, g_wa);
    float* wp; cudaGetSymbolAddress((void**)&wp, g_wp);
    float* yy; cudaGetSymbolAddress((void**)&yy, g_y);

    cudaFuncSetAttribute(gemm_cp<N_QKV, true>,
                         cudaFuncAttributeMaxDynamicSharedMemorySize, GEMM_SMEM);
    cudaFuncSetAttribute(gemm_cp<DD, false>,
                         cudaFuncAttributeMaxDynamicSharedMemorySize, GEMM_SMEM);
    cudaFuncSetAttribute(attn_mma2,
                         cudaFuncAttributeMaxDynamicSharedMemorySize, ATT2_SMEM);

    // 0) preconvert weights + x to tf32 fragment layouts
    conv_A<<<(MROWS/128) * NCHUNK * 32 / 8, 256>>>(x, xa);
    conv_B<N_QKV><<<(N_QKV/128) * NCHUNK * 64 / 8, 256>>>(w_attn, wa);
    conv_B<DD><<<(DD/128) * NCHUNK * 64 / 8, 256>>>(w_proj, wp);

    // 1) QKV projection (tensor cores, cp.async pipeline)
    gemm_cp<N_QKV, true><<<dim3(N_QKV / 128, MROWS / 128), 256, GEMM_SMEM>>>(
        xa, wa, b_attn, nullptr);

    // 2) convert Q/K/V to attention frag layouts
    conv_Qf<<<4096, 256>>>();
    conv_Kf<<<8192, 256>>>();
    conv_Vf<<<8192, 256>>>();

    // 3) causal flash attention (tensor cores, cp.async K/V)
    attn_mma2<<<dim3(SS / 128, BB * HH), 256, ATT2_SMEM>>>();

    // 4) convert attention output to A-frag layout
    conv_A<<<(MROWS/128) * NCHUNK * 32 / 8, 256>>>(yy, ya);

    // 5) output projection
    gemm_cp<DD, false><<<dim3(DD / 128, MROWS / 128), 256, GEMM_SMEM>>>(
        ya, wp, b_proj, out);
}

// round 8
// speedup vs baseline: 3.4380x; 1.0999x over previous
#include <cuda_runtime.h>
#include <cstdint>

#define BB 2
#define SS 2048
#define DD 1024
#define HH 16
#define HD 64
#define MROWS (BB*SS)   // 4096
#define N_QKV (3*DD)    // 3072
#define KDIM 1024
#define NCHUNK (KDIM/32)

// ---------------- device scratch (no allocation allowed) -------------------
// fragment-major tf32 buffers (bits stored as float)
__device__ __align__(128) float g_xa[MROWS/128 * NCHUNK * 4096];  // A-frag of x
__device__ __align__(128) float g_ya[MROWS/128 * NCHUNK * 4096];  // A-frag of attn out
__device__ __align__(128) float g_wa[N_QKV/128 * NCHUNK * 4096];  // B-frag of w_attn
__device__ __align__(128) float g_wp[DD/128   * NCHUNK * 4096];   // B-frag of w_proj
// attention frag buffers: per bh stride 131072 floats
__device__ __align__(128) float g_qf[32 * 131072];  // A-frag Q [bh][mb128][kb8][128]
__device__ __align__(128) float g_kf[32 * 131072];  // B-frag K [bh][sb256][kb8][64]
__device__ __align__(128) float g_vf[32 * 131072];  // B-frag V [bh][kt32][nb8][kb8][64]

__device__ __forceinline__ uint32_t f2tf(float x) {  // round-to-nearest tf32
    uint32_t r;
    asm("cvt.rna.tf32.f32 %0, %1;" : "=r"(r) : "f"(x));
    return r;
}
__device__ __forceinline__ float f2tff(float x) { return __uint_as_float(f2tf(x)); }

__device__ __forceinline__ uint32_t smem_u32(const void* p) {
    uint32_t a;
    asm("{ .reg .u64 t; cvta.to.shared.u64 t, %1; cvt.u32.u64 %0, t; }" : "=r"(a) : "l"(p));
    return a;
}

#define MMA_TF32(d, a, b) \
    asm volatile("mma.sync.aligned.m16n8k8.row.col.f32.tf32.tf32.f32 " \
        "{%0,%1,%2,%3}, {%4,%5,%6,%7}, {%8,%9}, {%0,%1,%2,%3};" \
        : "+f"((d)[0]), "+f"((d)[1]), "+f"((d)[2]), "+f"((d)[3]) \
        : "r"((a)[0]), "r"((a)[1]), "r"((a)[2]), "r"((a)[3]), \
          "r"((b)[0]), "r"((b)[1]))

#define CP16(dst, src) \
    asm volatile("cp.async.cg.shared.global [%0], [%1], 16;" :: "r"(dst), "l"(src) : "memory")
#define CP_COMMIT() asm volatile("cp.async.commit_group;" ::: "memory")
#define CP_WAIT1()  asm volatile("cp.async.wait_group 1;" ::: "memory")

// ---------------------------------------------------------------------------
// Direct fragment-layout scatter helpers (tf32 bits)
// ---------------------------------------------------------------------------
__device__ __forceinline__ void store_qkv_frag(int m, int n, float val) {
    const int b = m >> 11, s = m & 2047;
    const int which = n >> 10, h = (n >> 6) & 15, d = n & 63;
    const int bh = (b << 4) | h;
    const float tv = f2tff(val);
    if (which == 0) {        // Q A-frag: [bh][s>>4][d>>3][lane*4+reg]
        int off = bh * 131072 + (s >> 4) * 1024 + (d >> 3) * 128
                + (((s & 7) << 2) | (d & 3)) * 4
                + ((s & 8) ? 1 : 0) + ((d & 4) ? 2 : 0);
        g_qf[off] = tv;
    } else if (which == 1) { // K B-frag (n=s,k=d): [bh][s>>3][d>>3][lane*2+reg]
        int off = bh * 131072 + (s >> 3) * 512 + (d >> 3) * 64
                + (((s & 7) << 2) | (d & 3)) * 2 + ((d & 4) ? 1 : 0);
        g_kf[off] = tv;
    } else {                 // V B-frag (n=d,k=s): [bh][s>>6][d>>3][(s&63)>>3][lane*2+reg]
        int off = bh * 131072 + (s >> 6) * 4096 + (d >> 3) * 512 + ((s & 63) >> 3) * 64
                + (((d & 7) << 2) | (s & 3)) * 2 + ((s & 4) ? 1 : 0);
        g_vf[off] = tv;
    }
}

__device__ __forceinline__ void store_ya_frag(int m, int k, float val) {
    int off = (m >> 7) * 131072 + (k >> 5) * 4096 + ((m >> 4) & 7) * 512
            + ((k >> 3) & 3) * 128 + (((m & 7) << 2) | (k & 3)) * 4
            + ((m & 8) ? 1 : 0) + ((k & 4) ? 2 : 0);
    g_ya[off] = f2tff(val);
}

// ---------------------------------------------------------------------------
// Pre-conversion kernels (inputs only): fp32 -> tf32 fragment-major.
// ---------------------------------------------------------------------------
__global__ __launch_bounds__(256) void conv_A(const float* __restrict__ X,
                                              float* __restrict__ out) {
    int idx = blockIdx.x * 256 + threadIdx.x;
    int lane = idx & 31;
    int kb = (idx >> 5) & 3;
    int mb = (idx >> 7) & 7;
    int chunk = (idx >> 10) & 31;
    int mtile = idx >> 15;
    int r = lane >> 2, c = lane & 3;
    int m = mtile * 128 + mb * 16;
    int k = chunk * 32 + kb * 8;
    float4 v;
    v.x = f2tff(X[(size_t)(m + r) * KDIM + k + c]);
    v.y = f2tff(X[(size_t)(m + r + 8) * KDIM + k + c]);
    v.z = f2tff(X[(size_t)(m + r) * KDIM + k + c + 4]);
    v.w = f2tff(X[(size_t)(m + r + 8) * KDIM + k + c + 4]);
    *(float4*)(out + (size_t)idx * 4) = v;
}

template<int N>
__global__ __launch_bounds__(256) void conv_B(const float* __restrict__ W,
                                              float* __restrict__ out) {
    int idx = blockIdx.x * 256 + threadIdx.x;
    int lane = idx & 31;
    int kb = (idx >> 5) & 3;
    int nb = (idx >> 7) & 15;
    int chunk = (idx >> 11) & 31;
    int ntile = idx >> 16;
    int n = ntile * 128 + nb * 8 + (lane >> 2);
    int k = chunk * 32 + kb * 8 + (lane & 3);
    float2 v;
    v.x = f2tff(W[(size_t)k * N + n]);
    v.y = f2tff(W[(size_t)(k + 4) * N + n]);
    *(float2*)(out + (size_t)idx * 2) = v;
}

// ---------------------------------------------------------------------------
// GEMM: cp.async 3-stage pipeline (96KB smem -> 2 CTAs/SM).
// CTA 128x128, 8 warps (4m x 2n), warp tile 32x64.
// ---------------------------------------------------------------------------
#define GEMM_SMEM (3 * 32768)

template<int N, bool QKV>
__global__ __launch_bounds__(256, 2) void gemm_cp(const float* __restrict__ Afrag,
                                                  const float* __restrict__ Bfrag,
                                                  const float* __restrict__ bias,
                                                  float* __restrict__ Cout) {
    extern __shared__ float sm[];
    const uint32_t sb = smem_u32(sm);
    const int t = threadIdx.x;
    const int wid = t >> 5, lane = t & 31;
    const int warp_m = wid & 3, warp_n = wid >> 2;
    const int m0 = blockIdx.y * 128;
    const int n0 = blockIdx.x * 128;

    const float* Atile = Afrag + (size_t)blockIdx.y * (NCHUNK * 4096);
    const float* Btile = Bfrag + (size_t)blockIdx.x * (NCHUNK * 4096);

    float acc[2][8][4];
#pragma unroll
    for (int i = 0; i < 2; i++)
#pragma unroll
        for (int j = 0; j < 8; j++)
#pragma unroll
            for (int r = 0; r < 4; r++) acc[i][j][r] = 0.f;

#define ISSUE(c, s) do { \
        const float4* As_ = (const float4*)(Atile + (size_t)(c) * 4096) + t; \
        const float4* Bs_ = (const float4*)(Btile + (size_t)(c) * 4096) + t; \
        uint32_t d_ = sb + (uint32_t)(s) * 32768u + (uint32_t)t * 16u; \
        _Pragma("unroll") \
        for (int q = 0; q < 4; q++) CP16(d_ + q * 4096u, As_ + q * 256); \
        _Pragma("unroll") \
        for (int q = 0; q < 4; q++) CP16(d_ + 16384u + q * 4096u, Bs_ + q * 256); \
    } while (0)

    ISSUE(0, 0); CP_COMMIT();
    ISSUE(1, 1); CP_COMMIT();

    int stage = 0;   // buffer of chunk c
    int istage = 2;  // buffer of chunk c+2
#pragma unroll 1
    for (int c = 0; c < NCHUNK; c++) {
        CP_WAIT1();
        __syncthreads();
        const float* Ab = sm + stage * 8192;
        const float* Bb = Ab + 4096;
#pragma unroll
        for (int kb = 0; kb < 4; kb++) {
            uint32_t af[2][4], bf[8][2];
#pragma unroll
            for (int i = 0; i < 2; i++) {
                float4 v = *(const float4*)(Ab + ((warp_m * 2 + i) * 4 + kb) * 128 + lane * 4);
                af[i][0] = __float_as_uint(v.x); af[i][1] = __float_as_uint(v.y);
                af[i][2] = __float_as_uint(v.z); af[i][3] = __float_as_uint(v.w);
            }
#pragma unroll
            for (int j = 0; j < 8; j++) {
                float2 v = *(const float2*)(Bb + ((warp_n * 8 + j) * 4 + kb) * 64 + lane * 2);
                bf[j][0] = __float_as_uint(v.x); bf[j][1] = __float_as_uint(v.y);
            }
#pragma unroll
            for (int i = 0; i < 2; i++)
#pragma unroll
                for (int j = 0; j < 8; j++)
                    MMA_TF32(acc[i][j], af[i], bf[j]);
        }
        if (c + 2 < NCHUNK) ISSUE(c + 2, istage);
        CP_COMMIT();
        stage = (stage == 2) ? 0 : stage + 1;
        istage = (istage == 2) ? 0 : istage + 1;
    }
#undef ISSUE

    // Epilogue
    const int r0 = lane >> 2;
    const int cp = (lane & 3) * 2;
#pragma unroll
    for (int i = 0; i < 2; i++) {
        const int mbase = m0 + warp_m * 32 + i * 16;
        const int m1 = mbase + r0;
        const int m2 = m1 + 8;
#pragma unroll
        for (int j = 0; j < 8; j++) {
            const int n = n0 + warp_n * 64 + j * 8 + cp;
            const float bx = bias[n], by = bias[n + 1];
            if (QKV) {
                store_qkv_frag(m1, n,     acc[i][j][0] + bx);
                store_qkv_frag(m1, n + 1, acc[i][j][1] + by);
                store_qkv_frag(m2, n,     acc[i][j][2] + bx);
                store_qkv_frag(m2, n + 1, acc[i][j][3] + by);
            } else {
                *(float2*)(Cout + (size_t)m1 * DD + n) =
                    make_float2(acc[i][j][0] + bx, acc[i][j][1] + by);
                *(float2*)(Cout + (size_t)m2 * DD + n) =
                    make_float2(acc[i][j][2] + bx, acc[i][j][3] + by);
            }
        }
    }
}

// ---------------------------------------------------------------------------
// Flash attention: 256 threads (8 warps), q-tile 128 rows (warp owns 16),
// K/V 64-key tiles cp.async'd from frag buffers, double buffered.
// smem: KV[2][8192 floats] + P[8192 floats] = 96KB.
// ---------------------------------------------------------------------------
#define ATT2_SMEM (3 * 32768)

__global__ __launch_bounds__(256, 2) void attn_mma2() {
    extern __shared__ float sh[];
    const uint32_t sbase = smem_u32(sh);
    const int t = threadIdx.x;
    const int w = t >> 5, l = t & 31;
    const int qt = gridDim.x - 1 - blockIdx.x;   // heavy tiles first
    const int bh = blockIdx.y;

    const float* Qf  = g_qf + (size_t)bh * 131072 + (size_t)(qt * 8 + w) * 1024;
    const float* Kbh = g_kf + (size_t)bh * 131072;
    const float* Vbh = g_vf + (size_t)bh * 131072;

    uint32_t qa[8][4];
#pragma unroll
    for (int kb = 0; kb < 8; kb++) {
        float4 v = *(const float4*)(Qf + kb * 128 + l * 4);
        qa[kb][0] = __float_as_uint(v.x); qa[kb][1] = __float_as_uint(v.y);
        qa[kb][2] = __float_as_uint(v.z); qa[kb][3] = __float_as_uint(v.w);
    }

    float O[8][4];
#pragma unroll
    for (int j = 0; j < 8; j++)
#pragma unroll
        for (int r = 0; r < 4; r++) O[j][r] = 0.f;
    float m1 = -1e30f, m2 = -1e30f, l1 = 0.f, l2 = 0.f;

    const int ntiles = 2 * qt + 2;
    const int qrow_lo = qt * 128 + w * 16;
    const int qr1 = qrow_lo + (l >> 2);
    const int qr2 = qr1 + 8;

#define AISSUE(kt) do { \
        if ((kt) < ntiles) { \
            const float4* ks_ = (const float4*)(Kbh + (size_t)(kt) * 4096) + t; \
            const float4* vs_ = (const float4*)(Vbh + (size_t)(kt) * 4096) + t; \
            uint32_t db_ = sbase + ((kt) & 1) * 32768u + (uint32_t)t * 16u; \
            _Pragma("unroll") \
            for (int q = 0; q < 4; q++) CP16(db_ + q * 4096u, ks_ + q * 256); \
            _Pragma("unroll") \
            for (int q = 0; q < 4; q++) CP16(db_ + 16384u + q * 4096u, vs_ + q * 256); \
        } } while (0)

    AISSUE(0); CP_COMMIT();
    AISSUE(1); CP_COMMIT();

#pragma unroll 1
    for (int kt = 0; kt < ntiles; kt++) {
        CP_WAIT1();
        __syncthreads();

        const bool active = (kt * 64) <= (qrow_lo + 15);
        if (active) {
            const float* Kb = sh + (kt & 1) * 8192;
            const float* Vb = Kb + 4096;

            float S[8][4];
#pragma unroll
            for (int j = 0; j < 8; j++) {
#pragma unroll
                for (int r = 0; r < 4; r++) S[j][r] = 0.f;
#pragma unroll
                for (int kb = 0; kb < 8; kb++) {
                    float2 bv = *(const float2*)&Kb[(j * 8 + kb) * 64 + l * 2];
                    uint32_t bf[2] = {__float_as_uint(bv.x), __float_as_uint(bv.y)};
                    MMA_TF32(S[j], qa[kb], bf);
                }
            }

            const float sc = 0.125f;
            if (kt * 64 + 63 > qrow_lo) {
#pragma unroll
                for (int j = 0; j < 8; j++) {
                    int c0 = kt * 64 + j * 8 + (l & 3) * 2, c1 = c0 + 1;
                    S[j][0] = (c0 <= qr1) ? S[j][0] * sc : -1e30f;
                    S[j][1] = (c1 <= qr1) ? S[j][1] * sc : -1e30f;
                    S[j][2] = (c0 <= qr2) ? S[j][2] * sc : -1e30f;
                    S[j][3] = (c1 <= qr2) ? S[j][3] * sc : -1e30f;
                }
            } else {
#pragma unroll
                for (int j = 0; j < 8; j++)
#pragma unroll
                    for (int r = 0; r < 4; r++) S[j][r] *= sc;
            }

            float rm1 = -1e30f, rm2 = -1e30f;
#pragma unroll
            for (int j = 0; j < 8; j++) {
                rm1 = fmaxf(rm1, fmaxf(S[j][0], S[j][1]));
                rm2 = fmaxf(rm2, fmaxf(S[j][2], S[j][3]));
            }
            rm1 = fmaxf(rm1, __shfl_xor_sync(0xffffffffu, rm1, 1));
            rm1 = fmaxf(rm1, __shfl_xor_sync(0xffffffffu, rm1, 2));
            rm2 = fmaxf(rm2, __shfl_xor_sync(0xffffffffu, rm2, 1));
            rm2 = fmaxf(rm2, __shfl_xor_sync(0xffffffffu, rm2, 2));
            float mn1 = fmaxf(m1, rm1), mn2 = fmaxf(m2, rm2);
            float fi1 = __expf(m1 - mn1), fi2 = __expf(m2 - mn2);
            m1 = mn1; m2 = mn2;
            float rs1 = 0.f, rs2 = 0.f;
#pragma unroll
            for (int j = 0; j < 8; j++) {
                S[j][0] = __expf(S[j][0] - m1);
                S[j][1] = __expf(S[j][1] - m1);
                S[j][2] = __expf(S[j][2] - m2);
                S[j][3] = __expf(S[j][3] - m2);
                rs1 += S[j][0] + S[j][1];
                rs2 += S[j][2] + S[j][3];
            }
            rs1 += __shfl_xor_sync(0xffffffffu, rs1, 1);
            rs1 += __shfl_xor_sync(0xffffffffu, rs1, 2);
            rs2 += __shfl_xor_sync(0xffffffffu, rs2, 1);
            rs2 += __shfl_xor_sync(0xffffffffu, rs2, 2);
            l1 = l1 * fi1 + rs1;
            l2 = l2 * fi2 + rs2;
#pragma unroll
            for (int j = 0; j < 8; j++) {
                O[j][0] *= fi1; O[j][1] *= fi1;
                O[j][2] *= fi2; O[j][3] *= fi2;
            }

            {
                float* Pw = sh + 16384;
                const int r1 = l >> 2;
                const int c03 = ((l & 3) * 2) & 3;
                const int rotb = (l >> 1) & 3;
#pragma unroll
                for (int j = 0; j < 8; j++) {
                    int c0j = (l & 3) * 2;
                    int rgc = ((c0j & 7) >= 4) ? 2 : 0;
                    float* base = &Pw[(w * 8 + j) * 128 + (r1 * 4 + c03) * 4 + rgc];
                    float vals[4] = {S[j][0], S[j][2], S[j][1], S[j][3]};
#pragma unroll
                    for (int m = 0; m < 4; m++) {
                        int oi = (m + rotb) & 3;
                        int off = (oi & 1) + (oi >> 1) * 4;
                        base[off] = f2tff(vals[oi]);
                    }
                }
            }
            __syncwarp();

            {
                const float* Pw = sh + 16384;
                uint32_t pa[8][4];
#pragma unroll
                for (int kb = 0; kb < 8; kb++) {
                    float4 v = *(const float4*)&Pw[(w * 8 + kb) * 128 + l * 4];
                    pa[kb][0] = __float_as_uint(v.x); pa[kb][1] = __float_as_uint(v.y);
                    pa[kb][2] = __float_as_uint(v.z); pa[kb][3] = __float_as_uint(v.w);
                }
#pragma unroll
                for (int j = 0; j < 8; j++)
#pragma unroll
                    for (int kb = 0; kb < 8; kb++) {
                        float2 bv = *(const float2*)&Vb[(j * 8 + kb) * 64 + l * 2];
                        uint32_t bf[2] = {__float_as_uint(bv.x), __float_as_uint(bv.y)};
                        MMA_TF32(O[j], pa[kb], bf);
                    }
            }
        }

        __syncthreads();
        AISSUE(kt + 2);
        CP_COMMIT();
    }
#undef AISSUE

    // ---- epilogue: O /= l, write directly as A-frag for proj GEMM ----
    const int b = bh >> 4, h = bh & 15;
    const float inv1 = 1.f / l1, inv2 = 1.f / l2;
    const int mg1 = b * SS + qr1;
    const int mg2 = b * SS + qr2;
#pragma unroll
    for (int j = 0; j < 8; j++) {
        int c0 = j * 8 + (l & 3) * 2;
        int k = h * HD + c0;
        store_ya_frag(mg1, k,     O[j][0] * inv1);
        store_ya_frag(mg1, k + 1, O[j][1] * inv1);
        store_ya_frag(mg2, k,     O[j][2] * inv2);
        store_ya_frag(mg2, k + 1, O[j][3] * inv2);
    }
}

// ---------------------------------------------------------------------------

extern "C" void kernel_launch(void* const* d_in, const int* in_sizes, int n_in,
                              void* d_out, int out_size) {
    const float* x      = (const float*)d_in[0];  // [2,2048,1024]
    const float* w_attn = (const float*)d_in[1];  // [1024,3072]
    const float* b_attn = (const float*)d_in[2];  // [3072]
    const float* w_proj = (const float*)d_in[3];  // [1024,1024]
    const float* b_proj = (const float*)d_in[4];  // [1024]
    float* out = (float*)d_out;

    float* xa; cudaGetSymbolAddress((void**)&xa, g_xa);
    float* ya; cudaGetSymbolAddress((void**)&ya, g_ya);
    float* wa; cudaGetSymbolAddress((void**)&wa, g_wa);
    float* wp; cudaGetSymbolAddress((void**)&wp, g_wp);

    cudaFuncSetAttribute(gemm_cp<N_QKV, true>,
                         cudaFuncAttributeMaxDynamicSharedMemorySize, GEMM_SMEM);
    cudaFuncSetAttribute(gemm_cp<DD, false>,
                         cudaFuncAttributeMaxDynamicSharedMemorySize, GEMM_SMEM);
    cudaFuncSetAttribute(attn_mma2,
                         cudaFuncAttributeMaxDynamicSharedMemorySize, ATT2_SMEM);

    // 0) preconvert weights + x to tf32 fragment layouts
    conv_A<<<(MROWS/128) * NCHUNK * 32 / 8, 256>>>(x, xa);
    conv_B<N_QKV><<<(N_QKV/128) * NCHUNK * 64 / 8, 256>>>(w_attn, wa);
    conv_B<DD><<<(DD/128) * NCHUNK * 64 / 8, 256>>>(w_proj, wp);

    // 1) QKV projection -> writes Q/K/V frag buffers directly
    gemm_cp<N_QKV, true><<<dim3(N_QKV / 128, MROWS / 128), 256, GEMM_SMEM>>>(
        xa, wa, b_attn, nullptr);

    // 2) causal flash attention -> writes A-frag of y directly
    attn_mma2<<<dim3(SS / 128, BB * HH), 256, ATT2_SMEM>>>();

    // 3) output projection
    gemm_cp<DD, false><<<dim3(DD / 128, MROWS / 128), 256, GEMM_SMEM>>>(
        ya, wp, b_proj, out);
}

// round 9
// speedup vs baseline: 3.8263x; 1.1129x over previous
#include <cuda_runtime.h>
#include <cstdint>

#define BB 2
#define SS 2048
#define DD 1024
#define HH 16
#define HD 64
#define MROWS (BB*SS)   // 4096
#define N_QKV (3*DD)    // 3072
#define KDIM 1024
#define NCHUNK (KDIM/32)

// ---------------- device scratch (no allocation allowed) -------------------
// fragment-major tf32 buffers (bits stored as float)
__device__ __align__(128) float g_xa[MROWS/128 * NCHUNK * 4096];  // A-frag of x
__device__ __align__(128) float g_ya[MROWS/128 * NCHUNK * 4096];  // A-frag of attn out
__device__ __align__(128) float g_wa[N_QKV/128 * NCHUNK * 4096];  // B-frag of w_attn
__device__ __align__(128) float g_wp[DD/128   * NCHUNK * 4096];   // B-frag of w_proj
// attention frag buffers: per bh stride 131072 floats
__device__ __align__(128) float g_qf[32 * 131072];  // A-frag Q [bh][mb128][kb8][128]
__device__ __align__(128) float g_kf[32 * 131072];  // B-frag K [bh][sb256][kb8][64]
__device__ __align__(128) float g_vf[32 * 131072];  // B-frag V [bh][kt32][nb8][kb8][64]

__device__ __forceinline__ uint32_t f2tf(float x) {  // round-to-nearest tf32
    uint32_t r;
    asm("cvt.rna.tf32.f32 %0, %1;" : "=r"(r) : "f"(x));
    return r;
}
__device__ __forceinline__ float f2tff(float x) { return __uint_as_float(f2tf(x)); }

__device__ __forceinline__ uint32_t smem_u32(const void* p) {
    uint32_t a;
    asm("{ .reg .u64 t; cvta.to.shared.u64 t, %1; cvt.u32.u64 %0, t; }" : "=r"(a) : "l"(p));
    return a;
}

#define MMA_TF32(d, a, b) \
    asm volatile("mma.sync.aligned.m16n8k8.row.col.f32.tf32.tf32.f32 " \
        "{%0,%1,%2,%3}, {%4,%5,%6,%7}, {%8,%9}, {%0,%1,%2,%3};" \
        : "+f"((d)[0]), "+f"((d)[1]), "+f"((d)[2]), "+f"((d)[3]) \
        : "r"((a)[0]), "r"((a)[1]), "r"((a)[2]), "r"((a)[3]), \
          "r"((b)[0]), "r"((b)[1]))

#define CP16(dst, src) \
    asm volatile("cp.async.cg.shared.global [%0], [%1], 16;" :: "r"(dst), "l"(src) : "memory")
#define CP_COMMIT() asm volatile("cp.async.commit_group;" ::: "memory")
#define CP_WAIT1()  asm volatile("cp.async.wait_group 1;" ::: "memory")

// ---------------------------------------------------------------------------
// Direct fragment-layout scatter helpers (tf32 bits)
// ---------------------------------------------------------------------------
__device__ __forceinline__ void store_qkv_frag(int m, int n, float val) {
    const int b = m >> 11, s = m & 2047;
    const int which = n >> 10, h = (n >> 6) & 15, d = n & 63;
    const int bh = (b << 4) | h;
    const float tv = f2tff(val);
    if (which == 0) {        // Q A-frag
        int off = bh * 131072 + (s >> 4) * 1024 + (d >> 3) * 128
                + (((s & 7) << 2) | (d & 3)) * 4
                + ((s & 8) ? 1 : 0) + ((d & 4) ? 2 : 0);
        g_qf[off] = tv;
    } else if (which == 1) { // K B-frag (n=s,k=d)
        int off = bh * 131072 + (s >> 3) * 512 + (d >> 3) * 64
                + (((s & 7) << 2) | (d & 3)) * 2 + ((d & 4) ? 1 : 0);
        g_kf[off] = tv;
    } else {                 // V B-frag (n=d,k=s)
        int off = bh * 131072 + (s >> 6) * 4096 + (d >> 3) * 512 + ((s & 63) >> 3) * 64
                + (((d & 7) << 2) | (s & 3)) * 2 + ((s & 4) ? 1 : 0);
        g_vf[off] = tv;
    }
}

__device__ __forceinline__ void store_ya_frag(int m, int k, float val) {
    int off = (m >> 7) * 131072 + (k >> 5) * 4096 + ((m >> 4) & 7) * 512
            + ((k >> 3) & 3) * 128 + (((m & 7) << 2) | (k & 3)) * 4
            + ((m & 8) ? 1 : 0) + ((k & 4) ? 2 : 0);
    g_ya[off] = f2tff(val);
}

// ---------------------------------------------------------------------------
// Pre-conversion kernels (inputs only): fp32 -> tf32 fragment-major.
// ---------------------------------------------------------------------------
__global__ __launch_bounds__(256) void conv_A(const float* __restrict__ X,
                                              float* __restrict__ out) {
    int idx = blockIdx.x * 256 + threadIdx.x;
    int lane = idx & 31;
    int kb = (idx >> 5) & 3;
    int mb = (idx >> 7) & 7;
    int chunk = (idx >> 10) & 31;
    int mtile = idx >> 15;
    int r = lane >> 2, c = lane & 3;
    int m = mtile * 128 + mb * 16;
    int k = chunk * 32 + kb * 8;
    float4 v;
    v.x = f2tff(X[(size_t)(m + r) * KDIM + k + c]);
    v.y = f2tff(X[(size_t)(m + r + 8) * KDIM + k + c]);
    v.z = f2tff(X[(size_t)(m + r) * KDIM + k + c + 4]);
    v.w = f2tff(X[(size_t)(m + r + 8) * KDIM + k + c + 4]);
    *(float4*)(out + (size_t)idx * 4) = v;
}

template<int N>
__global__ __launch_bounds__(256) void conv_B(const float* __restrict__ W,
                                              float* __restrict__ out) {
    int idx = blockIdx.x * 256 + threadIdx.x;
    int lane = idx & 31;
    int kb = (idx >> 5) & 3;
    int nb = (idx >> 7) & 15;
    int chunk = (idx >> 11) & 31;
    int ntile = idx >> 16;
    int n = ntile * 128 + nb * 8 + (lane >> 2);
    int k = chunk * 32 + kb * 8 + (lane & 3);
    float2 v;
    v.x = f2tff(W[(size_t)k * N + n]);
    v.y = f2tff(W[(size_t)(k + 4) * N + n]);
    *(float2*)(out + (size_t)idx * 2) = v;
}

// ---------------------------------------------------------------------------
// GEMM: cp.async 3-stage pipeline (96KB smem -> 2 CTAs/SM), issue-early.
// ---------------------------------------------------------------------------
#define GEMM_SMEM (3 * 32768)

template<int N, bool QKV>
__global__ __launch_bounds__(256, 2) void gemm_cp(const float* __restrict__ Afrag,
                                                  const float* __restrict__ Bfrag,
                                                  const float* __restrict__ bias,
                                                  float* __restrict__ Cout) {
    extern __shared__ float sm[];
    const uint32_t sb = smem_u32(sm);
    const int t = threadIdx.x;
    const int wid = t >> 5, lane = t & 31;
    const int warp_m = wid & 3, warp_n = wid >> 2;
    const int m0 = blockIdx.y * 128;
    const int n0 = blockIdx.x * 128;

    const float* Atile = Afrag + (size_t)blockIdx.y * (NCHUNK * 4096);
    const float* Btile = Bfrag + (size_t)blockIdx.x * (NCHUNK * 4096);

    float acc[2][8][4];
#pragma unroll
    for (int i = 0; i < 2; i++)
#pragma unroll
        for (int j = 0; j < 8; j++)
#pragma unroll
            for (int r = 0; r < 4; r++) acc[i][j][r] = 0.f;

#define ISSUE(c, s) do { \
        const float4* As_ = (const float4*)(Atile + (size_t)(c) * 4096) + t; \
        const float4* Bs_ = (const float4*)(Btile + (size_t)(c) * 4096) + t; \
        uint32_t d_ = sb + (uint32_t)(s) * 32768u + (uint32_t)t * 16u; \
        _Pragma("unroll") \
        for (int q = 0; q < 4; q++) CP16(d_ + q * 4096u, As_ + q * 256); \
        _Pragma("unroll") \
        for (int q = 0; q < 4; q++) CP16(d_ + 16384u + q * 4096u, Bs_ + q * 256); \
    } while (0)

    ISSUE(0, 0); CP_COMMIT();
    ISSUE(1, 1); CP_COMMIT();

    int stage = 0;   // buffer of chunk c
    int istage = 2;  // buffer of chunk c+2
#pragma unroll 1
    for (int c = 0; c < NCHUNK; c++) {
        CP_WAIT1();
        __syncthreads();
        // issue-early: buffer istage was consumed at chunk c-1, covered by barrier
        if (c + 2 < NCHUNK) ISSUE(c + 2, istage);
        CP_COMMIT();

        const float* Ab = sm + stage * 8192;
        const float* Bb = Ab + 4096;
#pragma unroll
        for (int kb = 0; kb < 4; kb++) {
            uint32_t af[2][4], bf[8][2];
#pragma unroll
            for (int i = 0; i < 2; i++) {
                float4 v = *(const float4*)(Ab + ((warp_m * 2 + i) * 4 + kb) * 128 + lane * 4);
                af[i][0] = __float_as_uint(v.x); af[i][1] = __float_as_uint(v.y);
                af[i][2] = __float_as_uint(v.z); af[i][3] = __float_as_uint(v.w);
            }
#pragma unroll
            for (int j = 0; j < 8; j++) {
                float2 v = *(const float2*)(Bb + ((warp_n * 8 + j) * 4 + kb) * 64 + lane * 2);
                bf[j][0] = __float_as_uint(v.x); bf[j][1] = __float_as_uint(v.y);
            }
#pragma unroll
            for (int i = 0; i < 2; i++)
#pragma unroll
                for (int j = 0; j < 8; j++)
                    MMA_TF32(acc[i][j], af[i], bf[j]);
        }
        stage = (stage == 2) ? 0 : stage + 1;
        istage = (istage == 2) ? 0 : istage + 1;
    }
#undef ISSUE

    // Epilogue
    const int r0 = lane >> 2;
    const int cp = (lane & 3) * 2;
#pragma unroll
    for (int i = 0; i < 2; i++) {
        const int mbase = m0 + warp_m * 32 + i * 16;
        const int m1 = mbase + r0;
        const int m2 = m1 + 8;
#pragma unroll
        for (int j = 0; j < 8; j++) {
            const int n = n0 + warp_n * 64 + j * 8 + cp;
            const float bx = bias[n], by = bias[n + 1];
            if (QKV) {
                store_qkv_frag(m1, n,     acc[i][j][0] + bx);
                store_qkv_frag(m1, n + 1, acc[i][j][1] + by);
                store_qkv_frag(m2, n,     acc[i][j][2] + bx);
                store_qkv_frag(m2, n + 1, acc[i][j][3] + by);
            } else {
                *(float2*)(Cout + (size_t)m1 * DD + n) =
                    make_float2(acc[i][j][0] + bx, acc[i][j][1] + by);
                *(float2*)(Cout + (size_t)m2 * DD + n) =
                    make_float2(acc[i][j][2] + bx, acc[i][j][3] + by);
            }
        }
    }
}

// ---------------------------------------------------------------------------
// Flash attention v3: 3-buffer K/V, single barrier per tile, issue-early,
// shuffle-based P transpose (no P smem). smem = 3 x 32KB = 96KB.
// ---------------------------------------------------------------------------
#define ATT2_SMEM (3 * 32768)

__global__ __launch_bounds__(256, 2) void attn_mma2() {
    extern __shared__ float sh[];
    const uint32_t sbase = smem_u32(sh);
    const int t = threadIdx.x;
    const int w = t >> 5, l = t & 31;
    const int qt = gridDim.x - 1 - blockIdx.x;   // heavy tiles first
    const int bh = blockIdx.y;

    const float* Qf  = g_qf + (size_t)bh * 131072 + (size_t)(qt * 8 + w) * 1024;
    const float* Kbh = g_kf + (size_t)bh * 131072;
    const float* Vbh = g_vf + (size_t)bh * 131072;

    uint32_t qa[8][4];
#pragma unroll
    for (int kb = 0; kb < 8; kb++) {
        float4 v = *(const float4*)(Qf + kb * 128 + l * 4);
        qa[kb][0] = __float_as_uint(v.x); qa[kb][1] = __float_as_uint(v.y);
        qa[kb][2] = __float_as_uint(v.z); qa[kb][3] = __float_as_uint(v.w);
    }

    float O[8][4];
#pragma unroll
    for (int j = 0; j < 8; j++)
#pragma unroll
        for (int r = 0; r < 4; r++) O[j][r] = 0.f;
    float m1 = -1e30f, m2 = -1e30f, l1 = 0.f, l2 = 0.f;

    const int ntiles = 2 * qt + 2;
    const int qrow_lo = qt * 128 + w * 16;
    const int qr1 = qrow_lo + (l >> 2);
    const int qr2 = qr1 + 8;

    // shuffle-transpose source lanes (within quad group)
    const unsigned FULL = 0xffffffffu;
    const int sgrp = l & 0x1c;
    const int src0 = sgrp + ((l & 3) >> 1);
    const int src2 = src0 + 2;
    const bool oddl = (l & 1);

#define AISSUE(kt) do { \
        if ((kt) < ntiles) { \
            const float4* ks_ = (const float4*)(Kbh + (size_t)(kt) * 4096) + t; \
            const float4* vs_ = (const float4*)(Vbh + (size_t)(kt) * 4096) + t; \
            uint32_t db_ = sbase + (uint32_t)((kt) % 3) * 32768u + (uint32_t)t * 16u; \
            _Pragma("unroll") \
            for (int q = 0; q < 4; q++) CP16(db_ + q * 4096u, ks_ + q * 256); \
            _Pragma("unroll") \
            for (int q = 0; q < 4; q++) CP16(db_ + 16384u + q * 4096u, vs_ + q * 256); \
        } } while (0)

    AISSUE(0); CP_COMMIT();
    AISSUE(1); CP_COMMIT();

    int stage = 0, istage = 2;
#pragma unroll 1
    for (int kt = 0; kt < ntiles; kt++) {
        CP_WAIT1();
        __syncthreads();
        // issue-early into buffer consumed at kt-1 (covered by the barrier)
        AISSUE(kt + 2);
        CP_COMMIT();

        const bool active = (kt * 64) <= (qrow_lo + 15);
        if (active) {
            const float* Kb = sh + stage * 8192;
            const float* Vb = Kb + 4096;

            float S[8][4];
#pragma unroll
            for (int j = 0; j < 8; j++) {
#pragma unroll
                for (int r = 0; r < 4; r++) S[j][r] = 0.f;
#pragma unroll
                for (int kb = 0; kb < 8; kb++) {
                    float2 bv = *(const float2*)&Kb[(j * 8 + kb) * 64 + l * 2];
                    uint32_t bf[2] = {__float_as_uint(bv.x), __float_as_uint(bv.y)};
                    MMA_TF32(S[j], qa[kb], bf);
                }
            }

            const float sc = 0.125f;
            if (kt * 64 + 63 > qrow_lo) {
#pragma unroll
                for (int j = 0; j < 8; j++) {
                    int c0 = kt * 64 + j * 8 + (l & 3) * 2, c1 = c0 + 1;
                    S[j][0] = (c0 <= qr1) ? S[j][0] * sc : -1e30f;
                    S[j][1] = (c1 <= qr1) ? S[j][1] * sc : -1e30f;
                    S[j][2] = (c0 <= qr2) ? S[j][2] * sc : -1e30f;
                    S[j][3] = (c1 <= qr2) ? S[j][3] * sc : -1e30f;
                }
            } else {
#pragma unroll
                for (int j = 0; j < 8; j++)
#pragma unroll
                    for (int r = 0; r < 4; r++) S[j][r] *= sc;
            }

            float rm1 = -1e30f, rm2 = -1e30f;
#pragma unroll
            for (int j = 0; j < 8; j++) {
                rm1 = fmaxf(rm1, fmaxf(S[j][0], S[j][1]));
                rm2 = fmaxf(rm2, fmaxf(S[j][2], S[j][3]));
            }
            rm1 = fmaxf(rm1, __shfl_xor_sync(FULL, rm1, 1));
            rm1 = fmaxf(rm1, __shfl_xor_sync(FULL, rm1, 2));
            rm2 = fmaxf(rm2, __shfl_xor_sync(FULL, rm2, 1));
            rm2 = fmaxf(rm2, __shfl_xor_sync(FULL, rm2, 2));
            float mn1 = fmaxf(m1, rm1), mn2 = fmaxf(m2, rm2);
            float fi1 = __expf(m1 - mn1), fi2 = __expf(m2 - mn2);
            m1 = mn1; m2 = mn2;
            float rs1 = 0.f, rs2 = 0.f;
#pragma unroll
            for (int j = 0; j < 8; j++) {
                S[j][0] = __expf(S[j][0] - m1);
                S[j][1] = __expf(S[j][1] - m1);
                S[j][2] = __expf(S[j][2] - m2);
                S[j][3] = __expf(S[j][3] - m2);
                rs1 += S[j][0] + S[j][1];
                rs2 += S[j][2] + S[j][3];
            }
            rs1 += __shfl_xor_sync(FULL, rs1, 1);
            rs1 += __shfl_xor_sync(FULL, rs1, 2);
            rs2 += __shfl_xor_sync(FULL, rs2, 1);
            rs2 += __shfl_xor_sync(FULL, rs2, 2);
            l1 = l1 * fi1 + rs1;
            l2 = l2 * fi2 + rs2;
#pragma unroll
            for (int j = 0; j < 8; j++) {
                O[j][0] *= fi1; O[j][1] *= fi1;
                O[j][2] *= fi2; O[j][3] *= fi2;
            }

            // ---- shuffle transpose: S C-frag -> P A-frag (within quads) ----
            uint32_t pa[8][4];
#pragma unroll
            for (int j = 0; j < 8; j++) {
                float t0 = f2tff(S[j][0]), t1 = f2tff(S[j][1]);
                float t2 = f2tff(S[j][2]), t3 = f2tff(S[j][3]);
                float a0v0 = __shfl_sync(FULL, t0, src0);
                float a0v1 = __shfl_sync(FULL, t1, src0);
                float a1v0 = __shfl_sync(FULL, t2, src0);
                float a1v1 = __shfl_sync(FULL, t3, src0);
                float a2v0 = __shfl_sync(FULL, t0, src2);
                float a2v1 = __shfl_sync(FULL, t1, src2);
                float a3v0 = __shfl_sync(FULL, t2, src2);
                float a3v1 = __shfl_sync(FULL, t3, src2);
                pa[j][0] = __float_as_uint(oddl ? a0v1 : a0v0);
                pa[j][1] = __float_as_uint(oddl ? a1v1 : a1v0);
                pa[j][2] = __float_as_uint(oddl ? a2v1 : a2v0);
                pa[j][3] = __float_as_uint(oddl ? a3v1 : a3v0);
            }

            // ---- O += P @ V ----
#pragma unroll
            for (int j = 0; j < 8; j++)
#pragma unroll
                for (int kb = 0; kb < 8; kb++) {
                    float2 bv = *(const float2*)&Vb[(j * 8 + kb) * 64 + l * 2];
                    uint32_t bf[2] = {__float_as_uint(bv.x), __float_as_uint(bv.y)};
                    MMA_TF32(O[j], pa[kb], bf);
                }
        }

        stage = (stage == 2) ? 0 : stage + 1;
        istage = (istage == 2) ? 0 : istage + 1;
    }
#undef AISSUE

    // ---- epilogue: O /= l, write directly as A-frag for proj GEMM ----
    const int b = bh >> 4, h = bh & 15;
    const float inv1 = 1.f / l1, inv2 = 1.f / l2;
    const int mg1 = b * SS + qr1;
    const int mg2 = b * SS + qr2;
#pragma unroll
    for (int j = 0; j < 8; j++) {
        int c0 = j * 8 + (l & 3) * 2;
        int k = h * HD + c0;
        store_ya_frag(mg1, k,     O[j][0] * inv1);
        store_ya_frag(mg1, k + 1, O[j][1] * inv1);
        store_ya_frag(mg2, k,     O[j][2] * inv2);
        store_ya_frag(mg2, k + 1, O[j][3] * inv2);
    }
}

// ---------------------------------------------------------------------------

extern "C" void kernel_launch(void* const* d_in, const int* in_sizes, int n_in,
                              void* d_out, int out_size) {
    const float* x      = (const float*)d_in[0];  // [2,2048,1024]
    const float* w_attn = (const float*)d_in[1];  // [1024,3072]
    const float* b_attn = (const float*)d_in[2];  // [3072]
    const float* w_proj = (const float*)d_in[3];  // [1024,1024]
    const float* b_proj = (const float*)d_in[4];  // [1024]
    float* out = (float*)d_out;

    float* xa; cudaGetSymbolAddress((void**)&xa, g_xa);
    float* ya; cudaGetSymbolAddress((void**)&ya, g_ya);
    float* wa; cudaGetSymbolAddress((void**)&wa, g_wa);
    float* wp; cudaGetSymbolAddress((void**)&wp, g_wp);

    cudaFuncSetAttribute(gemm_cp<N_QKV, true>,
                         cudaFuncAttributeMaxDynamicSharedMemorySize, GEMM_SMEM);
    cudaFuncSetAttribute(gemm_cp<DD, false>,
                         cudaFuncAttributeMaxDynamicSharedMemorySize, GEMM_SMEM);
    cudaFuncSetAttribute(attn_mma2,
                         cudaFuncAttributeMaxDynamicSharedMemorySize, ATT2_SMEM);

    // 0) preconvert weights + x to tf32 fragment layouts
    conv_A<<<(MROWS/128) * NCHUNK * 32 / 8, 256>>>(x, xa);
    conv_B<N_QKV><<<(N_QKV/128) * NCHUNK * 64 / 8, 256>>>(w_attn, wa);
    conv_B<DD><<<(DD/128) * NCHUNK * 64 / 8, 256>>>(w_proj, wp);

    // 1) QKV projection -> writes Q/K/V frag buffers directly
    gemm_cp<N_QKV, true><<<dim3(N_QKV / 128, MROWS / 128), 256, GEMM_SMEM>>>(
        xa, wa, b_attn, nullptr);

    // 2) causal flash attention -> writes A-frag of y directly
    attn_mma2<<<dim3(SS / 128, BB * HH), 256, ATT2_SMEM>>>();

    // 3) output projection
    gemm_cp<DD, false><<<dim3(DD / 128, MROWS / 128), 256, GEMM_SMEM>>>(
        ya, wp, b_proj, out);
}